// round 11
// baseline (speedup 1.0000x reference)
#include <cuda_runtime.h>
#include <cuda_bf16.h>
#include <math.h>
#include <stdint.h>

// ---------------- constants ----------------
#define N_NODES  100000
#define N_EDGES  1600000
#define FEAT     128
#define N_GRAPHS 64
#define N_CLASSES 10

#define SCAN_BLK   1024
#define SCAN_NBLK  ((N_NODES + SCAN_BLK - 1) / SCAN_BLK)   // 98

// dynamic smem for sage_fused: agg tile 128x68 u32 + 3x 128x20 u32 = 65536 B
#define AGG_STR 68
#define WSTR    20
#define SMEM_DYN ((128 * AGG_STR + 3 * 128 * WSTR) * 4)

// ---------------- device scratch ----------------
__device__ __nv_bfloat16 g_B1[(size_t)N_NODES * FEAT];   // gcn gemm out; later final out
__device__ __nv_bfloat16 g_B2[(size_t)N_NODES * FEAT];   // gcn layer out (h1)
__device__ __nv_bfloat16 g_B3[(size_t)N_NODES * FEAT];   // sage1 out (h2)

// pre-split weights, k-major: [pair 0..63][row 0..127]
__device__ uint32_t g_Wg_hi[64 * 128],  g_Wg_lo[64 * 128];
__device__ uint32_t g_W1l_hi[64 * 128], g_W1l_lo[64 * 128];
__device__ uint32_t g_W1r_hi[64 * 128], g_W1r_lo[64 * 128];
__device__ uint32_t g_W2l_hi[64 * 128], g_W2l_lo[64 * 128];
__device__ uint32_t g_W2r_hi[64 * 128], g_W2r_lo[64 * 128];

__device__ int   g_src[N_EDGES];
__device__ int   g_dst[N_EDGES];
__device__ int   g_csr[N_EDGES];
__device__ int   g_batch[N_NODES];
__device__ int   g_indeg[N_NODES];
__device__ int   g_rowstart[N_NODES + 1];
__device__ int   g_pos[N_NODES];
__device__ float g_dinv[N_NODES];
__device__ float g_rcnt[N_NODES];
__device__ float g_pool[N_GRAPHS * FEAT];
__device__ int   g_gcnt[N_GRAPHS];
__device__ int   g_blocksum[SCAN_NBLK];
__device__ int   g_blockoff[SCAN_NBLK];
__device__ int   g_is64;

// ---------------- helpers ----------------
__device__ __forceinline__ void split2(float x, float y, uint32_t& hi, uint32_t& lo) {
    __nv_bfloat162 h = __floats2bfloat162_rn(x, y);
    float2 hf = __bfloat1622float2(h);
    __nv_bfloat162 l = __floats2bfloat162_rn(x - hf.x, y - hf.y);
    hi = *reinterpret_cast<uint32_t*>(&h);
    lo = *reinterpret_cast<uint32_t*>(&l);
}

__device__ __forceinline__ void mma_bf16(float* c, const uint32_t* a, const uint32_t* b) {
    asm volatile(
        "mma.sync.aligned.m16n8k16.row.col.f32.bf16.bf16.f32 "
        "{%0,%1,%2,%3}, {%4,%5,%6,%7}, {%8,%9}, {%0,%1,%2,%3};\n"
        : "+f"(c[0]), "+f"(c[1]), "+f"(c[2]), "+f"(c[3])
        : "r"(a[0]), "r"(a[1]), "r"(a[2]), "r"(a[3]), "r"(b[0]), "r"(b[1]));
}

__device__ __forceinline__ void acc_bf16row(float4& acc, const __nv_bfloat16* __restrict__ hb,
                                            int s, int lane, float nm) {
    uint2 raw = __ldg((const uint2*)(hb + (size_t)s * 128) + lane);
    float2 p0 = __bfloat1622float2(*reinterpret_cast<__nv_bfloat162*>(&raw.x));
    float2 p1 = __bfloat1622float2(*reinterpret_cast<__nv_bfloat162*>(&raw.y));
    acc.x += p0.x * nm; acc.y += p0.y * nm;
    acc.z += p1.x * nm; acc.w += p1.y * nm;
}

// ---------------- merged weight prepack ----------------
__global__ void prepack_all(const float* __restrict__ Wg,
                            const float* __restrict__ W1l, const float* __restrict__ W1r,
                            const float* __restrict__ W2l, const float* __restrict__ W2r)
{
    int widx = blockIdx.x >> 5;
    int idx  = (blockIdx.x & 31) * 256 + threadIdx.x;
    const float* W; uint32_t *hi, *lo;
    switch (widx) {
        case 0: W = Wg;  hi = g_Wg_hi;  lo = g_Wg_lo;  break;
        case 1: W = W1l; hi = g_W1l_hi; lo = g_W1l_lo; break;
        case 2: W = W1r; hi = g_W1r_hi; lo = g_W1r_lo; break;
        case 3: W = W2l; hi = g_W2l_hi; lo = g_W2l_lo; break;
        default:W = W2r; hi = g_W2r_hi; lo = g_W2r_lo; break;
    }
    int p = idx >> 7;
    int r = idx & 127;
    float x = W[r * 128 + p * 2];
    float y = W[r * 128 + p * 2 + 1];
    uint32_t h, l;
    split2(x, y, h, l);
    hi[p * 128 + r] = h;
    lo[p * 128 + r] = l;
}

// ---------------- index dtype detection ----------------
__global__ void detect_kernel(const void* ei) {
    const unsigned long long* p = (const unsigned long long*)ei;
    unsigned long long v = p[threadIdx.x];
    unsigned int hi = (unsigned int)(v >> 32);
    unsigned int any = __ballot_sync(0xffffffffu, hi != 0u);
    __shared__ int s_any;
    if (threadIdx.x == 0) s_any = 0;
    __syncthreads();
    if (any != 0u && (threadIdx.x & 31) == 0) atomicOr(&s_any, 1);
    __syncthreads();
    if (threadIdx.x == 0) g_is64 = s_any ? 0 : 1;
}

__global__ void zero_kernel() {
    int i = blockIdx.x * blockDim.x + threadIdx.x;
    if (i < N_NODES) g_indeg[i] = 0;
    if (i < N_GRAPHS * FEAT) g_pool[i] = 0.0f;
}

__global__ void convert_hist_kernel(const void* ei, const void* bt) {
    int i = blockIdx.x * blockDim.x + threadIdx.x;
    const int is64 = g_is64;
    if (i < N_EDGES) {
        int s, d;
        if (is64) {
            s = (int)((const long long*)ei)[i];
            d = (int)((const long long*)ei)[(size_t)N_EDGES + i];
        } else {
            s = ((const int*)ei)[i];
            d = ((const int*)ei)[N_EDGES + i];
        }
        g_src[i] = s;
        g_dst[i] = d;
        atomicAdd(&g_indeg[d], 1);
    }
    if (i < N_NODES) {
        g_batch[i] = is64 ? (int)((const long long*)bt)[i] : ((const int*)bt)[i];
    }
}

// ---------------- 3-phase multi-block scan ----------------
__global__ __launch_bounds__(SCAN_BLK) void scan1_kernel() {
    __shared__ int warp_s[32];
    int idx = blockIdx.x * SCAN_BLK + threadIdx.x;
    int v = (idx < N_NODES) ? g_indeg[idx] : 0;
#pragma unroll
    for (int o = 16; o > 0; o >>= 1) v += __shfl_down_sync(0xffffffffu, v, o);
    int wid = threadIdx.x >> 5, lane = threadIdx.x & 31;
    if (lane == 0) warp_s[wid] = v;
    __syncthreads();
    if (wid == 0) {
        int s = (lane < SCAN_BLK / 32) ? warp_s[lane] : 0;
#pragma unroll
        for (int o = 16; o > 0; o >>= 1) s += __shfl_down_sync(0xffffffffu, s, o);
        if (lane == 0) g_blocksum[blockIdx.x] = s;
    }
}

__global__ void scan2_kernel() {
    __shared__ int sm[SCAN_NBLK];
    int t = threadIdx.x;
    int v = (t < SCAN_NBLK) ? g_blocksum[t] : 0;
    if (t < SCAN_NBLK) sm[t] = v;
    __syncthreads();
    if (t == 0) {
        int run = 0;
        for (int i = 0; i < SCAN_NBLK; i++) { int c = sm[i]; sm[i] = run; run += c; }
        g_rowstart[N_NODES] = run;
    }
    __syncthreads();
    if (t < SCAN_NBLK) g_blockoff[t] = sm[t];
}

__global__ __launch_bounds__(SCAN_BLK) void scan3_kernel() {
    __shared__ int warp_s[32];
    int idx = blockIdx.x * SCAN_BLK + threadIdx.x;
    int wid = threadIdx.x >> 5, lane = threadIdx.x & 31;
    int c = (idx < N_NODES) ? g_indeg[idx] : 0;
    int v = c;
#pragma unroll
    for (int o = 1; o < 32; o <<= 1) {
        int u = __shfl_up_sync(0xffffffffu, v, o);
        if (lane >= o) v += u;
    }
    if (lane == 31) warp_s[wid] = v;
    __syncthreads();
    if (wid == 0) {
        int s = (lane < SCAN_BLK / 32) ? warp_s[lane] : 0;
#pragma unroll
        for (int o = 1; o < 32; o <<= 1) {
            int u = __shfl_up_sync(0xffffffffu, s, o);
            if (lane >= o) s += u;
        }
        if (lane < SCAN_BLK / 32) warp_s[lane] = s;
    }
    __syncthreads();
    int excl = v - c + (wid > 0 ? warp_s[wid - 1] : 0) + g_blockoff[blockIdx.x];
    if (idx < N_NODES) {
        g_rowstart[idx] = excl;
        g_pos[idx]      = excl;
        g_dinv[idx]     = rsqrtf((float)c + 1.0f);
        g_rcnt[idx]     = 1.0f / (float)max(c, 1);
    }
}

__global__ void scatter_kernel() {
    int e = blockIdx.x * blockDim.x + threadIdx.x;
    if (e < N_EDGES) {
        int d = g_dst[e];
        int p = atomicAdd(&g_pos[d], 1);
        g_csr[p] = g_src[e];
    }
}

// ---------------- GCN GEMM: A fp32 -> bf16 round; out bf16 ----------------
#define SMW 20
__global__ __launch_bounds__(256, 2) void gemm_gcn(
    const float* __restrict__ A,
    const uint32_t* __restrict__ Whi, const uint32_t* __restrict__ Wlo,
    __nv_bfloat16* __restrict__ outb, int M)
{
    __shared__ uint32_t sAh[128][SMW];
    __shared__ uint32_t sWhi[128][SMW], sWlo[128][SMW];

    const int t    = threadIdx.x;
    const int warp = t >> 5;
    const int lane = t & 31;
    const int wm   = warp >> 1;
    const int wn   = warp & 1;
    const int m0   = blockIdx.x * 128;
    const int r    = lane >> 2;
    const int kq   = lane & 3;

    float acc[2][8][4];
#pragma unroll
    for (int i = 0; i < 2; i++)
#pragma unroll
        for (int j = 0; j < 8; j++)
#pragma unroll
            for (int q = 0; q < 4; q++) acc[i][j][q] = 0.0f;

    for (int k0 = 0; k0 < 128; k0 += 32) {
#pragma unroll
        for (int i = 0; i < 4; i++) {
            int slot = t + i * 256;
            int row  = slot >> 3;
            int c4   = slot & 7;
            int ar   = m0 + row; if (ar >= M) ar = M - 1;
            float4 av = __ldg((const float4*)(A + (size_t)ar * 128 + k0 + c4 * 4));
            __nv_bfloat162 h0 = __floats2bfloat162_rn(av.x, av.y);
            __nv_bfloat162 h1 = __floats2bfloat162_rn(av.z, av.w);
            sAh[row][c4 * 2]     = *reinterpret_cast<uint32_t*>(&h0);
            sAh[row][c4 * 2 + 1] = *reinterpret_cast<uint32_t*>(&h1);
        }
        {
            int kb = k0 >> 1;
#pragma unroll
            for (int i = 0; i < 8; i++) {
                int idx = t + i * 256;
                int row = idx & 127;
                int w   = idx >> 7;
                sWhi[row][w] = __ldg(Whi + (kb + w) * 128 + row);
                sWlo[row][w] = __ldg(Wlo + (kb + w) * 128 + row);
            }
        }
        __syncthreads();

#pragma unroll
        for (int kk = 0; kk < 32; kk += 16) {
            const int kw = kk >> 1;
            uint32_t ah[2][4];
#pragma unroll
            for (int mt = 0; mt < 2; mt++) {
                int mr = wm * 32 + mt * 16;
                ah[mt][0] = sAh[mr + r][kw + kq];
                ah[mt][1] = sAh[mr + r + 8][kw + kq];
                ah[mt][2] = sAh[mr + r][kw + kq + 4];
                ah[mt][3] = sAh[mr + r + 8][kw + kq + 4];
            }
#pragma unroll
            for (int g = 0; g < 2; g++) {
                uint32_t bh[4][2], bl[4][2];
#pragma unroll
                for (int n2 = 0; n2 < 4; n2++) {
                    int nr = wn * 64 + g * 32 + n2 * 8 + r;
                    bh[n2][0] = sWhi[nr][kw + kq];
                    bh[n2][1] = sWhi[nr][kw + kq + 4];
                    bl[n2][0] = sWlo[nr][kw + kq];
                    bl[n2][1] = sWlo[nr][kw + kq + 4];
                }
#pragma unroll
                for (int mt = 0; mt < 2; mt++)
#pragma unroll
                    for (int n2 = 0; n2 < 4; n2++) {
                        float* c = acc[mt][g * 4 + n2];
                        mma_bf16(c, ah[mt], bh[n2]);
                        mma_bf16(c, ah[mt], bl[n2]);
                    }
            }
        }
        __syncthreads();
    }

#pragma unroll
    for (int mt = 0; mt < 2; mt++) {
#pragma unroll
        for (int nt = 0; nt < 8; nt++) {
            int gcol = wn * 64 + nt * 8 + kq * 2;
            int grow = m0 + wm * 32 + mt * 16 + r;
            if (grow < M)
                *(__nv_bfloat162*)(outb + (size_t)grow * 128 + gcol) =
                    __floats2bfloat162_rn(acc[mt][nt][0], acc[mt][nt][1]);
            int grow2 = grow + 8;
            if (grow2 < M)
                *(__nv_bfloat162*)(outb + (size_t)grow2 * 128 + gcol) =
                    __floats2bfloat162_rn(acc[mt][nt][2], acc[mt][nt][3]);
        }
    }
}

// ---------------- fused SAGE layer: gather-in-smem + dual MMA ----------------
// out = mean-agg(h)@Wl + bias + h@Wr   (all bf16 storage, fp32 accum)
__global__ __launch_bounds__(256, 2) void sage_fused(
    const __nv_bfloat16* __restrict__ h,
    const uint32_t* __restrict__ Wlhi, const uint32_t* __restrict__ Wllo,
    const uint32_t* __restrict__ Wrhi, const uint32_t* __restrict__ Wrlo,
    const float* __restrict__ bias,
    __nv_bfloat16* __restrict__ outb, int M)
{
    extern __shared__ uint32_t dyn[];
    uint32_t (*sAgg)[AGG_STR] = (uint32_t(*)[AGG_STR])dyn;                 // 128x68
    uint32_t (*sWhi)[WSTR] = (uint32_t(*)[WSTR])(dyn + 128 * AGG_STR);     // 128x20
    uint32_t (*sWlo)[WSTR] = (uint32_t(*)[WSTR])(dyn + 128 * AGG_STR + 128 * WSTR);
    uint32_t (*sAh)[WSTR]  = (uint32_t(*)[WSTR])(dyn + 128 * AGG_STR + 2 * 128 * WSTR);

    const int t    = threadIdx.x;
    const int warp = t >> 5;
    const int lane = t & 31;
    const int wm   = warp >> 1;
    const int wn   = warp & 1;
    const int m0   = blockIdx.x * 128;
    const int r    = lane >> 2;
    const int kq   = lane & 3;

    // ---- phase 1: each warp mean-aggregates 16 nodes into the smem agg tile ----
    for (int i = 0; i < 16; i++) {
        int lr = warp * 16 + i;
        int w  = m0 + lr;
        float4 acc4 = make_float4(0.f, 0.f, 0.f, 0.f);
        if (w < M) {
            int beg = g_rowstart[w], end = g_rowstart[w + 1];
            for (int b = beg; b < end; b += 32) {
                int nb = min(32, end - b);
                int s_l = 0;
                if (b + lane < end) s_l = g_csr[b + lane];
                for (int j = 0; j < nb; j++) {
                    int s = __shfl_sync(0xffffffffu, s_l, j);
                    acc_bf16row(acc4, h, s, lane, 1.0f);
                }
            }
            float rc = g_rcnt[w];
            acc4.x *= rc; acc4.y *= rc; acc4.z *= rc; acc4.w *= rc;
        }
        __nv_bfloat162 q0 = __floats2bfloat162_rn(acc4.x, acc4.y);
        __nv_bfloat162 q1 = __floats2bfloat162_rn(acc4.z, acc4.w);
        uint2 pk;
        pk.x = *reinterpret_cast<uint32_t*>(&q0);
        pk.y = *reinterpret_cast<uint32_t*>(&q1);
        *(uint2*)&sAgg[lr][lane * 2] = pk;
    }

    float acc[2][8][4];
#pragma unroll
    for (int i = 0; i < 2; i++)
#pragma unroll
        for (int j = 0; j < 8; j++)
#pragma unroll
            for (int q = 0; q < 4; q++) acc[i][j][q] = 0.0f;

    // ---- phase 2: pass 0 = agg@Wl (A resident), pass 1 = h@Wr (A streamed) ----
    for (int pass = 0; pass < 2; pass++) {
        const uint32_t* Whi = pass ? Wrhi : Wlhi;
        const uint32_t* Wlo = pass ? Wrlo : Wllo;
        for (int k0 = 0; k0 < 128; k0 += 32) {
            if (pass == 1) {
#pragma unroll
                for (int i = 0; i < 2; i++) {
                    int slot = t + i * 256;
                    int row  = slot >> 2;
                    int c16  = slot & 3;
                    int ar   = m0 + row; if (ar >= M) ar = M - 1;
                    uint4 v = __ldg((const uint4*)(h + (size_t)ar * 128 + k0) + c16);
                    *(uint4*)&sAh[row][c16 * 4] = v;
                }
            }
            {
                int kb = k0 >> 1;
#pragma unroll
                for (int i = 0; i < 8; i++) {
                    int idx = t + i * 256;
                    int row = idx & 127;
                    int w   = idx >> 7;
                    sWhi[row][w] = __ldg(Whi + (kb + w) * 128 + row);
                    sWlo[row][w] = __ldg(Wlo + (kb + w) * 128 + row);
                }
            }
            __syncthreads();

            const int base = k0 >> 1;
#pragma unroll
            for (int kk = 0; kk < 32; kk += 16) {
                const int kw = kk >> 1;
                uint32_t ah[2][4];
#pragma unroll
                for (int mt = 0; mt < 2; mt++) {
                    int mr = wm * 32 + mt * 16;
                    if (pass == 0) {
                        ah[mt][0] = sAgg[mr + r][base + kw + kq];
                        ah[mt][1] = sAgg[mr + r + 8][base + kw + kq];
                        ah[mt][2] = sAgg[mr + r][base + kw + kq + 4];
                        ah[mt][3] = sAgg[mr + r + 8][base + kw + kq + 4];
                    } else {
                        ah[mt][0] = sAh[mr + r][kw + kq];
                        ah[mt][1] = sAh[mr + r + 8][kw + kq];
                        ah[mt][2] = sAh[mr + r][kw + kq + 4];
                        ah[mt][3] = sAh[mr + r + 8][kw + kq + 4];
                    }
                }
#pragma unroll
                for (int g = 0; g < 2; g++) {
                    uint32_t bh[4][2], bl[4][2];
#pragma unroll
                    for (int n2 = 0; n2 < 4; n2++) {
                        int nr = wn * 64 + g * 32 + n2 * 8 + r;
                        bh[n2][0] = sWhi[nr][kw + kq];
                        bh[n2][1] = sWhi[nr][kw + kq + 4];
                        bl[n2][0] = sWlo[nr][kw + kq];
                        bl[n2][1] = sWlo[nr][kw + kq + 4];
                    }
#pragma unroll
                    for (int mt = 0; mt < 2; mt++)
#pragma unroll
                        for (int n2 = 0; n2 < 4; n2++) {
                            float* c = acc[mt][g * 4 + n2];
                            mma_bf16(c, ah[mt], bh[n2]);
                            mma_bf16(c, ah[mt], bl[n2]);
                        }
                }
            }
            __syncthreads();
        }
    }

    // ---- epilogue: + bias, store bf16 ----
#pragma unroll
    for (int mt = 0; mt < 2; mt++) {
#pragma unroll
        for (int nt = 0; nt < 8; nt++) {
            int gcol = wn * 64 + nt * 8 + kq * 2;
            float b0 = bias[gcol], b1 = bias[gcol + 1];
            int grow = m0 + wm * 32 + mt * 16 + r;
            if (grow < M)
                *(__nv_bfloat162*)(outb + (size_t)grow * 128 + gcol) =
                    __floats2bfloat162_rn(acc[mt][nt][0] + b0, acc[mt][nt][1] + b1);
            int grow2 = grow + 8;
            if (grow2 < M)
                *(__nv_bfloat162*)(outb + (size_t)grow2 * 128 + gcol) =
                    __floats2bfloat162_rn(acc[mt][nt][2] + b0, acc[mt][nt][3] + b1);
        }
    }
}

// ---------------- GCN gather (bf16 in, bf16 out) ----------------
__global__ __launch_bounds__(256) void gcn_gather_kernel(
    const __nv_bfloat16* __restrict__ xwb, __nv_bfloat16* __restrict__ outb,
    const float* __restrict__ bias)
{
    int w = (blockIdx.x * blockDim.x + threadIdx.x) >> 5;
    int lane = threadIdx.x & 31;
    if (w >= N_NODES) return;
    int beg = g_rowstart[w], end = g_rowstart[w + 1];
    float dn = g_dinv[w];
    float4 acc = make_float4(0.f, 0.f, 0.f, 0.f);
    for (int b = beg; b < end; b += 32) {
        int nb = min(32, end - b);
        int s_l = 0; float d_l = 0.f;
        if (b + lane < end) { s_l = g_csr[b + lane]; d_l = g_dinv[s_l]; }
        for (int j = 0; j < nb; j++) {
            int   s  = __shfl_sync(0xffffffffu, s_l, j);
            float nm = __shfl_sync(0xffffffffu, d_l, j) * dn;
            acc_bf16row(acc, xwb, s, lane, nm);
        }
    }
    float4 bv = *(const float4*)(bias + lane * 4);
    acc.x += bv.x; acc.y += bv.y; acc.z += bv.z; acc.w += bv.w;
    acc_bf16row(acc, xwb, w, lane, dn * dn);
    uint2 ob;
    __nv_bfloat162 q0 = __floats2bfloat162_rn(acc.x, acc.y);
    __nv_bfloat162 q1 = __floats2bfloat162_rn(acc.z, acc.w);
    ob.x = *reinterpret_cast<uint32_t*>(&q0);
    ob.y = *reinterpret_cast<uint32_t*>(&q1);
    *((uint2*)(outb + (size_t)w * 128) + lane) = ob;
}

// ---------------- pooling (bf16 input) ----------------
__device__ __forceinline__ int lower_bound_batch(int val) {
    int lo = 0, hi = N_NODES;
    while (lo < hi) {
        int mid = (lo + hi) >> 1;
        if (g_batch[mid] < val) lo = mid + 1; else hi = mid;
    }
    return lo;
}

__global__ void pool_kernel(const __nv_bfloat16* __restrict__ h) {
    int g = blockIdx.x;
    int part = blockIdx.y;
    int f = threadIdx.x;
    int lo = lower_bound_batch(g);
    int hi = lower_bound_batch(g + 1);
    float acc = 0.f;
    for (int n = lo + part; n < hi; n += 8)
        acc += __bfloat162float(h[(size_t)n * 128 + f]);
    atomicAdd(&g_pool[g * 128 + f], acc);
    if (part == 0 && f == 0) g_gcnt[g] = max(hi - lo, 1);
}

// ---------------- classifier MLP + softmax ----------------
__global__ void mlp_kernel(
    const float* __restrict__ w0, const float* __restrict__ b0,
    const float* __restrict__ w1, const float* __restrict__ b1,
    const float* __restrict__ w2, const float* __restrict__ b2,
    const float* __restrict__ w3, const float* __restrict__ b3,
    const float* __restrict__ bn0g, const float* __restrict__ bn0b,
    const float* __restrict__ bn1g, const float* __restrict__ bn1b,
    const float* __restrict__ bn2g, const float* __restrict__ bn2b,
    float* __restrict__ out)
{
    __shared__ float sin_[128], h0[200], h1[100], h2[50], lg[10];
    int g = blockIdx.x, t = threadIdx.x;
    if (t < 128) sin_[t] = g_pool[g * 128 + t] / (float)g_gcnt[g];
    __syncthreads();
    const float bnc = rsqrtf(1.0f + 1e-5f);
    if (t < 200) {
        float s = b0[t];
        const float* wr = w0 + (size_t)t * 128;
#pragma unroll 4
        for (int k = 0; k < 128; k++) s += wr[k] * sin_[k];
        h0[t] = tanhf(s * bn0g[t] * bnc + bn0b[t]);
    }
    __syncthreads();
    if (t < 100) {
        float s = b1[t];
        const float* wr = w1 + (size_t)t * 200;
#pragma unroll 4
        for (int k = 0; k < 200; k++) s += wr[k] * h0[k];
        h1[t] = tanhf(s * bn1g[t] * bnc + bn1b[t]);
    }
    __syncthreads();
    if (t < 50) {
        float s = b2[t];
        const float* wr = w2 + (size_t)t * 100;
#pragma unroll 4
        for (int k = 0; k < 100; k++) s += wr[k] * h1[k];
        h2[t] = tanhf(s * bn2g[t] * bnc + bn2b[t]);
    }
    __syncthreads();
    if (t < 10) {
        float s = b3[t];
        const float* wr = w3 + (size_t)t * 50;
#pragma unroll
        for (int k = 0; k < 50; k++) s += wr[k] * h2[k];
        lg[t] = s;
    }
    __syncthreads();
    if (t == 0) {
        float m = lg[0];
        for (int c = 1; c < N_CLASSES; c++) m = fmaxf(m, lg[c]);
        float e[N_CLASSES];
        float sum = 0.f;
        for (int c = 0; c < N_CLASSES; c++) { e[c] = expf(lg[c] - m); sum += e[c]; }
        float inv = 1.0f / sum;
        for (int c = 0; c < N_CLASSES; c++) out[g * N_CLASSES + c] = e[c] * inv;
    }
}

// ---------------- launch ----------------
extern "C" void kernel_launch(void* const* d_in, const int* in_sizes, int n_in,
                              void* d_out, int out_size)
{
    const float* x       = (const float*)d_in[0];
    const void*  ei      = d_in[1];
    const void*  bt      = d_in[2];
    const float* gcn_w   = (const float*)d_in[3];
    const float* gcn_b   = (const float*)d_in[4];
    const float* s1_wl   = (const float*)d_in[5];
    const float* s1_bl   = (const float*)d_in[6];
    const float* s1_wr   = (const float*)d_in[7];
    const float* s2_wl   = (const float*)d_in[8];
    const float* s2_bl   = (const float*)d_in[9];
    const float* s2_wr   = (const float*)d_in[10];
    const float* c_w0 = (const float*)d_in[11]; const float* c_b0 = (const float*)d_in[12];
    const float* c_w1 = (const float*)d_in[13]; const float* c_b1 = (const float*)d_in[14];
    const float* c_w2 = (const float*)d_in[15]; const float* c_b2 = (const float*)d_in[16];
    const float* c_w3 = (const float*)d_in[17]; const float* c_b3 = (const float*)d_in[18];
    const float* bn0g = (const float*)d_in[19]; const float* bn0b = (const float*)d_in[20];
    const float* bn1g = (const float*)d_in[21]; const float* bn1b = (const float*)d_in[22];
    const float* bn2g = (const float*)d_in[23]; const float* bn2b = (const float*)d_in[24];
    float* out = (float*)d_out;

    __nv_bfloat16 *B1, *B2, *B3;
    uint32_t *Wg_hi, *Wg_lo, *W1l_hi, *W1l_lo, *W1r_hi, *W1r_lo;
    uint32_t *W2l_hi, *W2l_lo, *W2r_hi, *W2r_lo;
    cudaGetSymbolAddress((void**)&B1, g_B1);
    cudaGetSymbolAddress((void**)&B2, g_B2);
    cudaGetSymbolAddress((void**)&B3, g_B3);
    cudaGetSymbolAddress((void**)&Wg_hi, g_Wg_hi);   cudaGetSymbolAddress((void**)&Wg_lo, g_Wg_lo);
    cudaGetSymbolAddress((void**)&W1l_hi, g_W1l_hi); cudaGetSymbolAddress((void**)&W1l_lo, g_W1l_lo);
    cudaGetSymbolAddress((void**)&W1r_hi, g_W1r_hi); cudaGetSymbolAddress((void**)&W1r_lo, g_W1r_lo);
    cudaGetSymbolAddress((void**)&W2l_hi, g_W2l_hi); cudaGetSymbolAddress((void**)&W2l_lo, g_W2l_lo);
    cudaGetSymbolAddress((void**)&W2r_hi, g_W2r_hi); cudaGetSymbolAddress((void**)&W2r_lo, g_W2r_lo);

    static cudaStream_t s_side = nullptr;
    static cudaEvent_t  s_fork = nullptr, s_join = nullptr;
    if (s_side == nullptr) {
        cudaStreamCreateWithFlags(&s_side, cudaStreamNonBlocking);
        cudaEventCreateWithFlags(&s_fork, cudaEventDisableTiming);
        cudaEventCreateWithFlags(&s_join, cudaEventDisableTiming);
        cudaFuncSetAttribute(sage_fused,
                             cudaFuncAttributeMaxDynamicSharedMemorySize, SMEM_DYN);
    }

    const int TB = 256;
    const int nodeBlocks   = (N_NODES + TB - 1) / TB;
    const int edgeBlocks   = (N_EDGES + TB - 1) / TB;
    const int gatherBlocks = (N_NODES + 7) / 8;
    const int gemmBlocks   = (N_NODES + 127) / 128;

    // fork at t=0: side stream does prepack + GCN GEMM, hidden under CSR build
    cudaEventRecord(s_fork, 0);
    cudaStreamWaitEvent(s_side, s_fork, 0);
    prepack_all<<<160, 256, 0, s_side>>>(gcn_w, s1_wl, s1_wr, s2_wl, s2_wr);
    gemm_gcn<<<gemmBlocks, 256, 0, s_side>>>(x, Wg_hi, Wg_lo, B1, N_NODES);

    // main stream: index prep + CSR build
    detect_kernel<<<1, 256>>>(ei);
    zero_kernel<<<nodeBlocks, TB>>>();
    convert_hist_kernel<<<edgeBlocks, TB>>>(ei, bt);
    scan1_kernel<<<SCAN_NBLK, SCAN_BLK>>>();
    scan2_kernel<<<1, 128>>>();
    scan3_kernel<<<SCAN_NBLK, SCAN_BLK>>>();
    scatter_kernel<<<edgeBlocks, TB>>>();

    cudaEventRecord(s_join, s_side);
    cudaStreamWaitEvent(0, s_join, 0);

    // GCN aggregate: B2 = norm-agg(B1) + self(B1)*dinv^2 + bias
    gcn_gather_kernel<<<gatherBlocks, 256>>>(B1, B2, gcn_b);

    // SAGE1 fused: B3 = mean-agg(B2)@W1l + bl + B2@W1r
    sage_fused<<<gemmBlocks, 256, SMEM_DYN>>>(B2, W1l_hi, W1l_lo, W1r_hi, W1r_lo,
                                              s1_bl, B3, N_NODES);

    // SAGE2 fused: B1 = mean-agg(B3)@W2l + bl + B3@W2r
    sage_fused<<<gemmBlocks, 256, SMEM_DYN>>>(B3, W2l_hi, W2l_lo, W2r_hi, W2r_lo,
                                              s2_bl, B1, N_NODES);

    // pool + classifier
    dim3 pg(N_GRAPHS, 8);
    pool_kernel<<<pg, 128>>>(B1);
    mlp_kernel<<<N_GRAPHS, 256>>>(c_w0, c_b0, c_w1, c_b1, c_w2, c_b2, c_w3, c_b3,
                                  bn0g, bn0b, bn1g, bn1b, bn2g, bn2b, out);
}

// round 12
// speedup vs baseline: 1.3214x; 1.3214x over previous
#include <cuda_runtime.h>
#include <cuda_bf16.h>
#include <math.h>
#include <stdint.h>

// ---------------- constants ----------------
#define N_NODES  100000
#define N_EDGES  1600000
#define FEAT     128
#define N_GRAPHS 64
#define N_CLASSES 10

#define SCAN_BLK   1024
#define SCAN_NBLK  ((N_NODES + SCAN_BLK - 1) / SCAN_BLK)   // 98

// ---------------- device scratch ----------------
__device__ __nv_bfloat16 g_B1[(size_t)N_NODES * FEAT];   // gcn gemm out; later final out
__device__ __nv_bfloat16 g_B2[(size_t)N_NODES * FEAT];   // gcn layer out (h1)
__device__ __nv_bfloat16 g_B3[(size_t)N_NODES * FEAT];   // sage1 out (h2)
__device__ __nv_bfloat16 g_Bagg[(size_t)N_NODES * FEAT]; // aggregation scratch

// pre-split weights, k-major: [pair 0..63][row 0..127]
__device__ uint32_t g_Wg_hi[64 * 128],  g_Wg_lo[64 * 128];
__device__ uint32_t g_W1l_hi[64 * 128], g_W1l_lo[64 * 128];
__device__ uint32_t g_W1r_hi[64 * 128], g_W1r_lo[64 * 128];
__device__ uint32_t g_W2l_hi[64 * 128], g_W2l_lo[64 * 128];
__device__ uint32_t g_W2r_hi[64 * 128], g_W2r_lo[64 * 128];

__device__ int   g_src[N_EDGES];
__device__ int   g_dst[N_EDGES];
__device__ int   g_csr[N_EDGES];
__device__ int   g_batch[N_NODES];
__device__ int   g_indeg[N_NODES];
__device__ int   g_rowstart[N_NODES + 1];
__device__ int   g_pos[N_NODES];
__device__ float g_dinv[N_NODES];
__device__ float g_rcnt[N_NODES];
__device__ float g_pool[N_GRAPHS * FEAT];
__device__ int   g_gcnt[N_GRAPHS];
__device__ int   g_blocksum[SCAN_NBLK];
__device__ int   g_blockoff[SCAN_NBLK];
__device__ int   g_is64;

// ---------------- helpers ----------------
__device__ __forceinline__ void split2(float x, float y, uint32_t& hi, uint32_t& lo) {
    __nv_bfloat162 h = __floats2bfloat162_rn(x, y);
    float2 hf = __bfloat1622float2(h);
    __nv_bfloat162 l = __floats2bfloat162_rn(x - hf.x, y - hf.y);
    hi = *reinterpret_cast<uint32_t*>(&h);
    lo = *reinterpret_cast<uint32_t*>(&l);
}

__device__ __forceinline__ void mma_bf16(float* c, const uint32_t* a, const uint32_t* b) {
    asm volatile(
        "mma.sync.aligned.m16n8k16.row.col.f32.bf16.bf16.f32 "
        "{%0,%1,%2,%3}, {%4,%5,%6,%7}, {%8,%9}, {%0,%1,%2,%3};\n"
        : "+f"(c[0]), "+f"(c[1]), "+f"(c[2]), "+f"(c[3])
        : "r"(a[0]), "r"(a[1]), "r"(a[2]), "r"(a[3]), "r"(b[0]), "r"(b[1]));
}

__device__ __forceinline__ void acc_bf16row(float4& acc, const __nv_bfloat16* __restrict__ hb,
                                            int s, int lane, float nm) {
    uint2 raw = __ldg((const uint2*)(hb + (size_t)s * 128) + lane);
    float2 p0 = __bfloat1622float2(*reinterpret_cast<__nv_bfloat162*>(&raw.x));
    float2 p1 = __bfloat1622float2(*reinterpret_cast<__nv_bfloat162*>(&raw.y));
    acc.x += p0.x * nm; acc.y += p0.y * nm;
    acc.z += p1.x * nm; acc.w += p1.y * nm;
}

__device__ __forceinline__ void store_bf16row(__nv_bfloat16* __restrict__ outb,
                                              int w, int lane, const float4& acc) {
    uint2 ob;
    __nv_bfloat162 q0 = __floats2bfloat162_rn(acc.x, acc.y);
    __nv_bfloat162 q1 = __floats2bfloat162_rn(acc.z, acc.w);
    ob.x = *reinterpret_cast<uint32_t*>(&q0);
    ob.y = *reinterpret_cast<uint32_t*>(&q1);
    *((uint2*)(outb + (size_t)w * 128) + lane) = ob;
}

// ---------------- merged weight prepack (5 matrices in one launch) ----------------
__global__ void prepack_all(const float* __restrict__ Wg,
                            const float* __restrict__ W1l, const float* __restrict__ W1r,
                            const float* __restrict__ W2l, const float* __restrict__ W2r)
{
    int widx = blockIdx.x >> 5;
    int idx  = (blockIdx.x & 31) * 256 + threadIdx.x;
    const float* W; uint32_t *hi, *lo;
    switch (widx) {
        case 0: W = Wg;  hi = g_Wg_hi;  lo = g_Wg_lo;  break;
        case 1: W = W1l; hi = g_W1l_hi; lo = g_W1l_lo; break;
        case 2: W = W1r; hi = g_W1r_hi; lo = g_W1r_lo; break;
        case 3: W = W2l; hi = g_W2l_hi; lo = g_W2l_lo; break;
        default:W = W2r; hi = g_W2r_hi; lo = g_W2r_lo; break;
    }
    int p = idx >> 7;
    int r = idx & 127;
    float x = W[r * 128 + p * 2];
    float y = W[r * 128 + p * 2 + 1];
    uint32_t h, l;
    split2(x, y, h, l);
    hi[p * 128 + r] = h;
    lo[p * 128 + r] = l;
}

// ---------------- index dtype detection ----------------
__global__ void detect_kernel(const void* ei) {
    const unsigned long long* p = (const unsigned long long*)ei;
    unsigned long long v = p[threadIdx.x];
    unsigned int hi = (unsigned int)(v >> 32);
    unsigned int any = __ballot_sync(0xffffffffu, hi != 0u);
    __shared__ int s_any;
    if (threadIdx.x == 0) s_any = 0;
    __syncthreads();
    if (any != 0u && (threadIdx.x & 31) == 0) atomicOr(&s_any, 1);
    __syncthreads();
    if (threadIdx.x == 0) g_is64 = s_any ? 0 : 1;
}

__global__ void zero_kernel() {
    int i = blockIdx.x * blockDim.x + threadIdx.x;
    if (i < N_NODES) g_indeg[i] = 0;
    if (i < N_GRAPHS * FEAT) g_pool[i] = 0.0f;
}

__global__ void convert_hist_kernel(const void* ei, const void* bt) {
    int i = blockIdx.x * blockDim.x + threadIdx.x;
    const int is64 = g_is64;
    if (i < N_EDGES) {
        int s, d;
        if (is64) {
            s = (int)((const long long*)ei)[i];
            d = (int)((const long long*)ei)[(size_t)N_EDGES + i];
        } else {
            s = ((const int*)ei)[i];
            d = ((const int*)ei)[N_EDGES + i];
        }
        g_src[i] = s;
        g_dst[i] = d;
        atomicAdd(&g_indeg[d], 1);
    }
    if (i < N_NODES) {
        g_batch[i] = is64 ? (int)((const long long*)bt)[i] : ((const int*)bt)[i];
    }
}

// ---------------- 3-phase multi-block scan ----------------
__global__ __launch_bounds__(SCAN_BLK) void scan1_kernel() {
    __shared__ int warp_s[32];
    int idx = blockIdx.x * SCAN_BLK + threadIdx.x;
    int v = (idx < N_NODES) ? g_indeg[idx] : 0;
#pragma unroll
    for (int o = 16; o > 0; o >>= 1) v += __shfl_down_sync(0xffffffffu, v, o);
    int wid = threadIdx.x >> 5, lane = threadIdx.x & 31;
    if (lane == 0) warp_s[wid] = v;
    __syncthreads();
    if (wid == 0) {
        int s = (lane < SCAN_BLK / 32) ? warp_s[lane] : 0;
#pragma unroll
        for (int o = 16; o > 0; o >>= 1) s += __shfl_down_sync(0xffffffffu, s, o);
        if (lane == 0) g_blocksum[blockIdx.x] = s;
    }
}

__global__ void scan2_kernel() {
    __shared__ int sm[SCAN_NBLK];
    int t = threadIdx.x;
    int v = (t < SCAN_NBLK) ? g_blocksum[t] : 0;
    if (t < SCAN_NBLK) sm[t] = v;
    __syncthreads();
    if (t == 0) {
        int run = 0;
        for (int i = 0; i < SCAN_NBLK; i++) { int c = sm[i]; sm[i] = run; run += c; }
        g_rowstart[N_NODES] = run;
    }
    __syncthreads();
    if (t < SCAN_NBLK) g_blockoff[t] = sm[t];
}

__global__ __launch_bounds__(SCAN_BLK) void scan3_kernel() {
    __shared__ int warp_s[32];
    int idx = blockIdx.x * SCAN_BLK + threadIdx.x;
    int wid = threadIdx.x >> 5, lane = threadIdx.x & 31;
    int c = (idx < N_NODES) ? g_indeg[idx] : 0;
    int v = c;
#pragma unroll
    for (int o = 1; o < 32; o <<= 1) {
        int u = __shfl_up_sync(0xffffffffu, v, o);
        if (lane >= o) v += u;
    }
    if (lane == 31) warp_s[wid] = v;
    __syncthreads();
    if (wid == 0) {
        int s = (lane < SCAN_BLK / 32) ? warp_s[lane] : 0;
#pragma unroll
        for (int o = 1; o < 32; o <<= 1) {
            int u = __shfl_up_sync(0xffffffffu, s, o);
            if (lane >= o) s += u;
        }
        if (lane < SCAN_BLK / 32) warp_s[lane] = s;
    }
    __syncthreads();
    int excl = v - c + (wid > 0 ? warp_s[wid - 1] : 0) + g_blockoff[blockIdx.x];
    if (idx < N_NODES) {
        g_rowstart[idx] = excl;
        g_pos[idx]      = excl;
        g_dinv[idx]     = rsqrtf((float)c + 1.0f);
        g_rcnt[idx]     = 1.0f / (float)max(c, 1);
    }
}

__global__ void scatter_kernel() {
    int e = blockIdx.x * blockDim.x + threadIdx.x;
    if (e < N_EDGES) {
        int d = g_dst[e];
        int p = atomicAdd(&g_pos[d], 1);
        g_csr[p] = g_src[e];
    }
}

// ---------------- GCN GEMM: A fp32 -> bf16 round; out bf16 ----------------
#define SMW 20
__global__ __launch_bounds__(256, 2) void gemm_gcn(
    const float* __restrict__ A,
    const uint32_t* __restrict__ Whi, const uint32_t* __restrict__ Wlo,
    __nv_bfloat16* __restrict__ outb, int M)
{
    __shared__ uint32_t sAh[128][SMW];
    __shared__ uint32_t sWhi[128][SMW], sWlo[128][SMW];

    const int t    = threadIdx.x;
    const int warp = t >> 5;
    const int lane = t & 31;
    const int wm   = warp >> 1;
    const int wn   = warp & 1;
    const int m0   = blockIdx.x * 128;
    const int r    = lane >> 2;
    const int kq   = lane & 3;

    float acc[2][8][4];
#pragma unroll
    for (int i = 0; i < 2; i++)
#pragma unroll
        for (int j = 0; j < 8; j++)
#pragma unroll
            for (int q = 0; q < 4; q++) acc[i][j][q] = 0.0f;

    for (int k0 = 0; k0 < 128; k0 += 32) {
#pragma unroll
        for (int i = 0; i < 4; i++) {
            int slot = t + i * 256;
            int row  = slot >> 3;
            int c4   = slot & 7;
            int ar   = m0 + row; if (ar >= M) ar = M - 1;
            float4 av = __ldg((const float4*)(A + (size_t)ar * 128 + k0 + c4 * 4));
            __nv_bfloat162 h0 = __floats2bfloat162_rn(av.x, av.y);
            __nv_bfloat162 h1 = __floats2bfloat162_rn(av.z, av.w);
            sAh[row][c4 * 2]     = *reinterpret_cast<uint32_t*>(&h0);
            sAh[row][c4 * 2 + 1] = *reinterpret_cast<uint32_t*>(&h1);
        }
        {
            int kb = k0 >> 1;
#pragma unroll
            for (int i = 0; i < 8; i++) {
                int idx = t + i * 256;
                int row = idx & 127;
                int w   = idx >> 7;
                sWhi[row][w] = __ldg(Whi + (kb + w) * 128 + row);
                sWlo[row][w] = __ldg(Wlo + (kb + w) * 128 + row);
            }
        }
        __syncthreads();

#pragma unroll
        for (int kk = 0; kk < 32; kk += 16) {
            const int kw = kk >> 1;
            uint32_t ah[2][4];
#pragma unroll
            for (int mt = 0; mt < 2; mt++) {
                int mr = wm * 32 + mt * 16;
                ah[mt][0] = sAh[mr + r][kw + kq];
                ah[mt][1] = sAh[mr + r + 8][kw + kq];
                ah[mt][2] = sAh[mr + r][kw + kq + 4];
                ah[mt][3] = sAh[mr + r + 8][kw + kq + 4];
            }
#pragma unroll
            for (int g = 0; g < 2; g++) {
                uint32_t bh[4][2], bl[4][2];
#pragma unroll
                for (int n2 = 0; n2 < 4; n2++) {
                    int nr = wn * 64 + g * 32 + n2 * 8 + r;
                    bh[n2][0] = sWhi[nr][kw + kq];
                    bh[n2][1] = sWhi[nr][kw + kq + 4];
                    bl[n2][0] = sWlo[nr][kw + kq];
                    bl[n2][1] = sWlo[nr][kw + kq + 4];
                }
#pragma unroll
                for (int mt = 0; mt < 2; mt++)
#pragma unroll
                    for (int n2 = 0; n2 < 4; n2++) {
                        float* c = acc[mt][g * 4 + n2];
                        mma_bf16(c, ah[mt], bh[n2]);
                        mma_bf16(c, ah[mt], bl[n2]);
                    }
            }
        }
        __syncthreads();
    }

#pragma unroll
    for (int mt = 0; mt < 2; mt++) {
#pragma unroll
        for (int nt = 0; nt < 8; nt++) {
            int gcol = wn * 64 + nt * 8 + kq * 2;
            int grow = m0 + wm * 32 + mt * 16 + r;
            if (grow < M)
                *(__nv_bfloat162*)(outb + (size_t)grow * 128 + gcol) =
                    __floats2bfloat162_rn(acc[mt][nt][0], acc[mt][nt][1]);
            int grow2 = grow + 8;
            if (grow2 < M)
                *(__nv_bfloat162*)(outb + (size_t)grow2 * 128 + gcol) =
                    __floats2bfloat162_rn(acc[mt][nt][2], acc[mt][nt][3]);
        }
    }
}

// ---------------- dual GEMM: A1,A2 bf16; out = A1@W1 + A2@W2 + bias (bf16 out) ----
__global__ __launch_bounds__(256, 2) void gemm_dual(
    const __nv_bfloat16* __restrict__ A1,
    const uint32_t* __restrict__ W1hi, const uint32_t* __restrict__ W1lo,
    const __nv_bfloat16* __restrict__ A2,
    const uint32_t* __restrict__ W2hi, const uint32_t* __restrict__ W2lo,
    const float* __restrict__ bias,
    __nv_bfloat16* __restrict__ outb, int M)
{
    __shared__ uint32_t sAh[128][SMW];
    __shared__ uint32_t sWhi[128][SMW], sWlo[128][SMW];

    const int t    = threadIdx.x;
    const int warp = t >> 5;
    const int lane = t & 31;
    const int wm   = warp >> 1;
    const int wn   = warp & 1;
    const int m0   = blockIdx.x * 128;
    const int r    = lane >> 2;
    const int kq   = lane & 3;

    float acc[2][8][4];
#pragma unroll
    for (int i = 0; i < 2; i++)
#pragma unroll
        for (int j = 0; j < 8; j++)
#pragma unroll
            for (int q = 0; q < 4; q++) acc[i][j][q] = 0.0f;

    for (int pass = 0; pass < 2; pass++) {
        const __nv_bfloat16* A = pass ? A2 : A1;
        const uint32_t* Whi = pass ? W2hi : W1hi;
        const uint32_t* Wlo = pass ? W2lo : W1lo;
        for (int k0 = 0; k0 < 128; k0 += 32) {
#pragma unroll
            for (int i = 0; i < 2; i++) {
                int slot = t + i * 256;
                int row  = slot >> 2;
                int c16  = slot & 3;
                int ar   = m0 + row; if (ar >= M) ar = M - 1;
                uint4 v = __ldg((const uint4*)(A + (size_t)ar * 128 + k0) + c16);
                *(uint4*)&sAh[row][c16 * 4] = v;
            }
            {
                int kb = k0 >> 1;
#pragma unroll
                for (int i = 0; i < 8; i++) {
                    int idx = t + i * 256;
                    int row = idx & 127;
                    int w   = idx >> 7;
                    sWhi[row][w] = __ldg(Whi + (kb + w) * 128 + row);
                    sWlo[row][w] = __ldg(Wlo + (kb + w) * 128 + row);
                }
            }
            __syncthreads();

#pragma unroll
            for (int kk = 0; kk < 32; kk += 16) {
                const int kw = kk >> 1;
                uint32_t ah[2][4];
#pragma unroll
                for (int mt = 0; mt < 2; mt++) {
                    int mr = wm * 32 + mt * 16;
                    ah[mt][0] = sAh[mr + r][kw + kq];
                    ah[mt][1] = sAh[mr + r + 8][kw + kq];
                    ah[mt][2] = sAh[mr + r][kw + kq + 4];
                    ah[mt][3] = sAh[mr + r + 8][kw + kq + 4];
                }
#pragma unroll
                for (int g = 0; g < 2; g++) {
                    uint32_t bh[4][2], bl[4][2];
#pragma unroll
                    for (int n2 = 0; n2 < 4; n2++) {
                        int nr = wn * 64 + g * 32 + n2 * 8 + r;
                        bh[n2][0] = sWhi[nr][kw + kq];
                        bh[n2][1] = sWhi[nr][kw + kq + 4];
                        bl[n2][0] = sWlo[nr][kw + kq];
                        bl[n2][1] = sWlo[nr][kw + kq + 4];
                    }
#pragma unroll
                    for (int mt = 0; mt < 2; mt++)
#pragma unroll
                        for (int n2 = 0; n2 < 4; n2++) {
                            float* c = acc[mt][g * 4 + n2];
                            mma_bf16(c, ah[mt], bh[n2]);
                            mma_bf16(c, ah[mt], bl[n2]);
                        }
                }
            }
            __syncthreads();
        }
    }

#pragma unroll
    for (int mt = 0; mt < 2; mt++) {
#pragma unroll
        for (int nt = 0; nt < 8; nt++) {
            int gcol = wn * 64 + nt * 8 + kq * 2;
            float b0 = bias[gcol], b1 = bias[gcol + 1];
            int grow = m0 + wm * 32 + mt * 16 + r;
            if (grow < M)
                *(__nv_bfloat162*)(outb + (size_t)grow * 128 + gcol) =
                    __floats2bfloat162_rn(acc[mt][nt][0] + b0, acc[mt][nt][1] + b1);
            int grow2 = grow + 8;
            if (grow2 < M)
                *(__nv_bfloat162*)(outb + (size_t)grow2 * 128 + gcol) =
                    __floats2bfloat162_rn(acc[mt][nt][2] + b0, acc[mt][nt][3] + b1);
        }
    }
}

// ---------------- CSR gathers (bf16 in, bf16 out, fp32 accumulate) ----------------
__global__ __launch_bounds__(256) void gcn_gather_kernel(
    const __nv_bfloat16* __restrict__ xwb, __nv_bfloat16* __restrict__ outb,
    const float* __restrict__ bias)
{
    int w = (blockIdx.x * blockDim.x + threadIdx.x) >> 5;
    int lane = threadIdx.x & 31;
    if (w >= N_NODES) return;
    int beg = g_rowstart[w], end = g_rowstart[w + 1];
    float dn = g_dinv[w];
    float4 acc = make_float4(0.f, 0.f, 0.f, 0.f);
    for (int b = beg; b < end; b += 32) {
        int nb = min(32, end - b);
        int s_l = 0; float d_l = 0.f;
        if (b + lane < end) { s_l = g_csr[b + lane]; d_l = g_dinv[s_l]; }
        for (int j = 0; j < nb; j++) {
            int   s  = __shfl_sync(0xffffffffu, s_l, j);
            float nm = __shfl_sync(0xffffffffu, d_l, j) * dn;
            acc_bf16row(acc, xwb, s, lane, nm);
        }
    }
    float4 bv = *(const float4*)(bias + lane * 4);
    acc.x += bv.x; acc.y += bv.y; acc.z += bv.z; acc.w += bv.w;
    acc_bf16row(acc, xwb, w, lane, dn * dn);
    store_bf16row(outb, w, lane, acc);
}

__global__ __launch_bounds__(256) void sage_gather_kernel(
    const __nv_bfloat16* __restrict__ hb, __nv_bfloat16* __restrict__ outb)
{
    int w = (blockIdx.x * blockDim.x + threadIdx.x) >> 5;
    int lane = threadIdx.x & 31;
    if (w >= N_NODES) return;
    int beg = g_rowstart[w], end = g_rowstart[w + 1];
    float4 acc = make_float4(0.f, 0.f, 0.f, 0.f);
    for (int b = beg; b < end; b += 32) {
        int nb = min(32, end - b);
        int s_l = 0;
        if (b + lane < end) s_l = g_csr[b + lane];
        for (int j = 0; j < nb; j++) {
            int s = __shfl_sync(0xffffffffu, s_l, j);
            acc_bf16row(acc, hb, s, lane, 1.0f);
        }
    }
    float rc = g_rcnt[w];
    acc.x *= rc; acc.y *= rc; acc.z *= rc; acc.w *= rc;
    store_bf16row(outb, w, lane, acc);
}

// ---------------- pooling (bf16 input) ----------------
__device__ __forceinline__ int lower_bound_batch(int val) {
    int lo = 0, hi = N_NODES;
    while (lo < hi) {
        int mid = (lo + hi) >> 1;
        if (g_batch[mid] < val) lo = mid + 1; else hi = mid;
    }
    return lo;
}

__global__ void pool_kernel(const __nv_bfloat16* __restrict__ h) {
    int g = blockIdx.x;
    int part = blockIdx.y;
    int f = threadIdx.x;
    int lo = lower_bound_batch(g);
    int hi = lower_bound_batch(g + 1);
    float acc = 0.f;
    for (int n = lo + part; n < hi; n += 8)
        acc += __bfloat162float(h[(size_t)n * 128 + f]);
    atomicAdd(&g_pool[g * 128 + f], acc);
    if (part == 0 && f == 0) g_gcnt[g] = max(hi - lo, 1);
}

// ---------------- classifier MLP + softmax ----------------
__global__ void mlp_kernel(
    const float* __restrict__ w0, const float* __restrict__ b0,
    const float* __restrict__ w1, const float* __restrict__ b1,
    const float* __restrict__ w2, const float* __restrict__ b2,
    const float* __restrict__ w3, const float* __restrict__ b3,
    const float* __restrict__ bn0g, const float* __restrict__ bn0b,
    const float* __restrict__ bn1g, const float* __restrict__ bn1b,
    const float* __restrict__ bn2g, const float* __restrict__ bn2b,
    float* __restrict__ out)
{
    __shared__ float sin_[128], h0[200], h1[100], h2[50], lg[10];
    int g = blockIdx.x, t = threadIdx.x;
    if (t < 128) sin_[t] = g_pool[g * 128 + t] / (float)g_gcnt[g];
    __syncthreads();
    const float bnc = rsqrtf(1.0f + 1e-5f);
    if (t < 200) {
        float s = b0[t];
        const float* wr = w0 + (size_t)t * 128;
#pragma unroll 4
        for (int k = 0; k < 128; k++) s += wr[k] * sin_[k];
        h0[t] = tanhf(s * bn0g[t] * bnc + bn0b[t]);
    }
    __syncthreads();
    if (t < 100) {
        float s = b1[t];
        const float* wr = w1 + (size_t)t * 200;
#pragma unroll 4
        for (int k = 0; k < 200; k++) s += wr[k] * h0[k];
        h1[t] = tanhf(s * bn1g[t] * bnc + bn1b[t]);
    }
    __syncthreads();
    if (t < 50) {
        float s = b2[t];
        const float* wr = w2 + (size_t)t * 100;
#pragma unroll 4
        for (int k = 0; k < 100; k++) s += wr[k] * h1[k];
        h2[t] = tanhf(s * bn2g[t] * bnc + bn2b[t]);
    }
    __syncthreads();
    if (t < 10) {
        float s = b3[t];
        const float* wr = w3 + (size_t)t * 50;
#pragma unroll
        for (int k = 0; k < 50; k++) s += wr[k] * h2[k];
        lg[t] = s;
    }
    __syncthreads();
    if (t == 0) {
        float m = lg[0];
        for (int c = 1; c < N_CLASSES; c++) m = fmaxf(m, lg[c]);
        float e[N_CLASSES];
        float sum = 0.f;
        for (int c = 0; c < N_CLASSES; c++) { e[c] = expf(lg[c] - m); sum += e[c]; }
        float inv = 1.0f / sum;
        for (int c = 0; c < N_CLASSES; c++) out[g * N_CLASSES + c] = e[c] * inv;
    }
}

// ---------------- launch ----------------
extern "C" void kernel_launch(void* const* d_in, const int* in_sizes, int n_in,
                              void* d_out, int out_size)
{
    const float* x       = (const float*)d_in[0];
    const void*  ei      = d_in[1];
    const void*  bt      = d_in[2];
    const float* gcn_w   = (const float*)d_in[3];
    const float* gcn_b   = (const float*)d_in[4];
    const float* s1_wl   = (const float*)d_in[5];
    const float* s1_bl   = (const float*)d_in[6];
    const float* s1_wr   = (const float*)d_in[7];
    const float* s2_wl   = (const float*)d_in[8];
    const float* s2_bl   = (const float*)d_in[9];
    const float* s2_wr   = (const float*)d_in[10];
    const float* c_w0 = (const float*)d_in[11]; const float* c_b0 = (const float*)d_in[12];
    const float* c_w1 = (const float*)d_in[13]; const float* c_b1 = (const float*)d_in[14];
    const float* c_w2 = (const float*)d_in[15]; const float* c_b2 = (const float*)d_in[16];
    const float* c_w3 = (const float*)d_in[17]; const float* c_b3 = (const float*)d_in[18];
    const float* bn0g = (const float*)d_in[19]; const float* bn0b = (const float*)d_in[20];
    const float* bn1g = (const float*)d_in[21]; const float* bn1b = (const float*)d_in[22];
    const float* bn2g = (const float*)d_in[23]; const float* bn2b = (const float*)d_in[24];
    float* out = (float*)d_out;

    __nv_bfloat16 *B1, *B2, *B3, *Bagg;
    uint32_t *Wg_hi, *Wg_lo, *W1l_hi, *W1l_lo, *W1r_hi, *W1r_lo;
    uint32_t *W2l_hi, *W2l_lo, *W2r_hi, *W2r_lo;
    cudaGetSymbolAddress((void**)&B1, g_B1);
    cudaGetSymbolAddress((void**)&B2, g_B2);
    cudaGetSymbolAddress((void**)&B3, g_B3);
    cudaGetSymbolAddress((void**)&Bagg, g_Bagg);
    cudaGetSymbolAddress((void**)&Wg_hi, g_Wg_hi);   cudaGetSymbolAddress((void**)&Wg_lo, g_Wg_lo);
    cudaGetSymbolAddress((void**)&W1l_hi, g_W1l_hi); cudaGetSymbolAddress((void**)&W1l_lo, g_W1l_lo);
    cudaGetSymbolAddress((void**)&W1r_hi, g_W1r_hi); cudaGetSymbolAddress((void**)&W1r_lo, g_W1r_lo);
    cudaGetSymbolAddress((void**)&W2l_hi, g_W2l_hi); cudaGetSymbolAddress((void**)&W2l_lo, g_W2l_lo);
    cudaGetSymbolAddress((void**)&W2r_hi, g_W2r_hi); cudaGetSymbolAddress((void**)&W2r_lo, g_W2r_lo);

    static cudaStream_t s_side = nullptr;
    static cudaEvent_t  s_fork = nullptr, s_join = nullptr;
    if (s_side == nullptr) {
        cudaStreamCreateWithFlags(&s_side, cudaStreamNonBlocking);
        cudaEventCreateWithFlags(&s_fork, cudaEventDisableTiming);
        cudaEventCreateWithFlags(&s_join, cudaEventDisableTiming);
    }

    const int TB = 256;
    const int nodeBlocks   = (N_NODES + TB - 1) / TB;
    const int edgeBlocks   = (N_EDGES + TB - 1) / TB;
    const int gatherBlocks = (N_NODES + 7) / 8;
    const int gemmBlocks   = (N_NODES + 127) / 128;

    // fork at t=0: side stream does prepack + GCN GEMM, hidden under CSR build
    cudaEventRecord(s_fork, 0);
    cudaStreamWaitEvent(s_side, s_fork, 0);
    prepack_all<<<160, 256, 0, s_side>>>(gcn_w, s1_wl, s1_wr, s2_wl, s2_wr);
    gemm_gcn<<<gemmBlocks, 256, 0, s_side>>>(x, Wg_hi, Wg_lo, B1, N_NODES);

    // main stream: index prep + CSR build
    detect_kernel<<<1, 256>>>(ei);
    zero_kernel<<<nodeBlocks, TB>>>();
    convert_hist_kernel<<<edgeBlocks, TB>>>(ei, bt);
    scan1_kernel<<<SCAN_NBLK, SCAN_BLK>>>();
    scan2_kernel<<<1, 128>>>();
    scan3_kernel<<<SCAN_NBLK, SCAN_BLK>>>();
    scatter_kernel<<<edgeBlocks, TB>>>();

    cudaEventRecord(s_join, s_side);
    cudaStreamWaitEvent(0, s_join, 0);

    // GCN aggregate: B2 = norm-agg(B1) + self(B1)*dinv^2 + bias
    gcn_gather_kernel<<<gatherBlocks, 256>>>(B1, B2, gcn_b);

    // SAGE1: Bagg = mean-agg(B2); B3 = Bagg@W1l + bl + B2@W1r
    sage_gather_kernel<<<gatherBlocks, 256>>>(B2, Bagg);
    gemm_dual<<<gemmBlocks, 256>>>(Bagg, W1l_hi, W1l_lo, B2, W1r_hi, W1r_lo,
                                   s1_bl, B3, N_NODES);

    // SAGE2: Bagg = mean-agg(B3); B1 = Bagg@W2l + bl + B3@W2r (bf16 out for pool)
    sage_gather_kernel<<<gatherBlocks, 256>>>(B3, Bagg);
    gemm_dual<<<gemmBlocks, 256>>>(Bagg, W2l_hi, W2l_lo, B3, W2r_hi, W2r_lo,
                                   s2_bl, B1, N_NODES);

    // pool + classifier
    dim3 pg(N_GRAPHS, 8);
    pool_kernel<<<pg, 128>>>(B1);
    mlp_kernel<<<N_GRAPHS, 256>>>(c_w0, c_b0, c_w1, c_b1, c_w2, c_b2, c_w3, c_b3,
                                  bn0g, bn0b, bn1g, bn1b, bn2g, bn2b, out);
}

// round 13
// speedup vs baseline: 1.3543x; 1.0249x over previous
#include <cuda_runtime.h>
#include <cuda_bf16.h>
#include <math.h>
#include <stdint.h>

// ---------------- constants ----------------
#define N_NODES  100000
#define N_EDGES  1600000
#define FEAT     128
#define N_GRAPHS 64
#define N_CLASSES 10

#define SCAN_BLK   1024
#define SCAN_NBLK  ((N_NODES + SCAN_BLK - 1) / SCAN_BLK)   // 98

// gemm_dual dynamic smem: full W (hi+lo, 128x68 u32 each) + double-buffered A (2x128x20)
#define WF_STR 68
#define A_STR  20
#define GEMM_SMEM ((2 * 128 * WF_STR + 2 * 128 * A_STR) * 4)   // 90112 B

// ---------------- device scratch ----------------
__device__ __nv_bfloat16 g_B1[(size_t)N_NODES * FEAT];   // gcn gemm out; later final out
__device__ __nv_bfloat16 g_B2[(size_t)N_NODES * FEAT];   // gcn layer out (h1)
__device__ __nv_bfloat16 g_B3[(size_t)N_NODES * FEAT];   // sage1 out (h2)
__device__ __nv_bfloat16 g_Bagg[(size_t)N_NODES * FEAT]; // aggregation scratch

// pre-split weights, k-major: [pair 0..63][row 0..127]
__device__ uint32_t g_Wg_hi[64 * 128],  g_Wg_lo[64 * 128];
__device__ uint32_t g_W1l_hi[64 * 128], g_W1l_lo[64 * 128];
__device__ uint32_t g_W1r_hi[64 * 128], g_W1r_lo[64 * 128];
__device__ uint32_t g_W2l_hi[64 * 128], g_W2l_lo[64 * 128];
__device__ uint32_t g_W2r_hi[64 * 128], g_W2r_lo[64 * 128];

__device__ int   g_src[N_EDGES];
__device__ int   g_dst[N_EDGES];
__device__ int   g_csr[N_EDGES];
__device__ int   g_batch[N_NODES];
__device__ int   g_indeg[N_NODES];
__device__ int   g_rowstart[N_NODES + 1];
__device__ int   g_pos[N_NODES];
__device__ float g_dinv[N_NODES];
__device__ float g_rcnt[N_NODES];
__device__ float g_pool[N_GRAPHS * FEAT];
__device__ int   g_gcnt[N_GRAPHS];
__device__ int   g_blocksum[SCAN_NBLK];
__device__ int   g_blockoff[SCAN_NBLK];
__device__ int   g_is64;

// ---------------- helpers ----------------
__device__ __forceinline__ void split2(float x, float y, uint32_t& hi, uint32_t& lo) {
    __nv_bfloat162 h = __floats2bfloat162_rn(x, y);
    float2 hf = __bfloat1622float2(h);
    __nv_bfloat162 l = __floats2bfloat162_rn(x - hf.x, y - hf.y);
    hi = *reinterpret_cast<uint32_t*>(&h);
    lo = *reinterpret_cast<uint32_t*>(&l);
}

__device__ __forceinline__ void mma_bf16(float* c, const uint32_t* a, const uint32_t* b) {
    asm volatile(
        "mma.sync.aligned.m16n8k16.row.col.f32.bf16.bf16.f32 "
        "{%0,%1,%2,%3}, {%4,%5,%6,%7}, {%8,%9}, {%0,%1,%2,%3};\n"
        : "+f"(c[0]), "+f"(c[1]), "+f"(c[2]), "+f"(c[3])
        : "r"(a[0]), "r"(a[1]), "r"(a[2]), "r"(a[3]), "r"(b[0]), "r"(b[1]));
}

__device__ __forceinline__ void acc_bf16row(float4& acc, const __nv_bfloat16* __restrict__ hb,
                                            int s, int lane, float nm) {
    uint2 raw = __ldg((const uint2*)(hb + (size_t)s * 128) + lane);
    float2 p0 = __bfloat1622float2(*reinterpret_cast<__nv_bfloat162*>(&raw.x));
    float2 p1 = __bfloat1622float2(*reinterpret_cast<__nv_bfloat162*>(&raw.y));
    acc.x += p0.x * nm; acc.y += p0.y * nm;
    acc.z += p1.x * nm; acc.w += p1.y * nm;
}

__device__ __forceinline__ void store_bf16row(__nv_bfloat16* __restrict__ outb,
                                              int w, int lane, const float4& acc) {
    uint2 ob;
    __nv_bfloat162 q0 = __floats2bfloat162_rn(acc.x, acc.y);
    __nv_bfloat162 q1 = __floats2bfloat162_rn(acc.z, acc.w);
    ob.x = *reinterpret_cast<uint32_t*>(&q0);
    ob.y = *reinterpret_cast<uint32_t*>(&q1);
    *((uint2*)(outb + (size_t)w * 128) + lane) = ob;
}

// ---------------- merged weight prepack ----------------
__global__ void prepack_all(const float* __restrict__ Wg,
                            const float* __restrict__ W1l, const float* __restrict__ W1r,
                            const float* __restrict__ W2l, const float* __restrict__ W2r)
{
    int widx = blockIdx.x >> 5;
    int idx  = (blockIdx.x & 31) * 256 + threadIdx.x;
    const float* W; uint32_t *hi, *lo;
    switch (widx) {
        case 0: W = Wg;  hi = g_Wg_hi;  lo = g_Wg_lo;  break;
        case 1: W = W1l; hi = g_W1l_hi; lo = g_W1l_lo; break;
        case 2: W = W1r; hi = g_W1r_hi; lo = g_W1r_lo; break;
        case 3: W = W2l; hi = g_W2l_hi; lo = g_W2l_lo; break;
        default:W = W2r; hi = g_W2r_hi; lo = g_W2r_lo; break;
    }
    int p = idx >> 7;
    int r = idx & 127;
    float x = W[r * 128 + p * 2];
    float y = W[r * 128 + p * 2 + 1];
    uint32_t h, l;
    split2(x, y, h, l);
    hi[p * 128 + r] = h;
    lo[p * 128 + r] = l;
}

// ---------------- index dtype detection ----------------
__global__ void detect_kernel(const void* ei) {
    const unsigned long long* p = (const unsigned long long*)ei;
    unsigned long long v = p[threadIdx.x];
    unsigned int hi = (unsigned int)(v >> 32);
    unsigned int any = __ballot_sync(0xffffffffu, hi != 0u);
    __shared__ int s_any;
    if (threadIdx.x == 0) s_any = 0;
    __syncthreads();
    if (any != 0u && (threadIdx.x & 31) == 0) atomicOr(&s_any, 1);
    __syncthreads();
    if (threadIdx.x == 0) g_is64 = s_any ? 0 : 1;
}

__global__ void zero_kernel() {
    int i = blockIdx.x * blockDim.x + threadIdx.x;
    if (i < N_NODES) g_indeg[i] = 0;
    if (i < N_GRAPHS * FEAT) g_pool[i] = 0.0f;
}

__global__ void convert_hist_kernel(const void* ei, const void* bt) {
    int i = blockIdx.x * blockDim.x + threadIdx.x;
    const int is64 = g_is64;
    if (i < N_EDGES) {
        int s, d;
        if (is64) {
            s = (int)((const long long*)ei)[i];
            d = (int)((const long long*)ei)[(size_t)N_EDGES + i];
        } else {
            s = ((const int*)ei)[i];
            d = ((const int*)ei)[N_EDGES + i];
        }
        g_src[i] = s;
        g_dst[i] = d;
        atomicAdd(&g_indeg[d], 1);
    }
    if (i < N_NODES) {
        g_batch[i] = is64 ? (int)((const long long*)bt)[i] : ((const int*)bt)[i];
    }
}

// ---------------- 3-phase multi-block scan ----------------
__global__ __launch_bounds__(SCAN_BLK) void scan1_kernel() {
    __shared__ int warp_s[32];
    int idx = blockIdx.x * SCAN_BLK + threadIdx.x;
    int v = (idx < N_NODES) ? g_indeg[idx] : 0;
#pragma unroll
    for (int o = 16; o > 0; o >>= 1) v += __shfl_down_sync(0xffffffffu, v, o);
    int wid = threadIdx.x >> 5, lane = threadIdx.x & 31;
    if (lane == 0) warp_s[wid] = v;
    __syncthreads();
    if (wid == 0) {
        int s = (lane < SCAN_BLK / 32) ? warp_s[lane] : 0;
#pragma unroll
        for (int o = 16; o > 0; o >>= 1) s += __shfl_down_sync(0xffffffffu, s, o);
        if (lane == 0) g_blocksum[blockIdx.x] = s;
    }
}

__global__ void scan2_kernel() {
    __shared__ int sm[SCAN_NBLK];
    int t = threadIdx.x;
    int v = (t < SCAN_NBLK) ? g_blocksum[t] : 0;
    if (t < SCAN_NBLK) sm[t] = v;
    __syncthreads();
    if (t == 0) {
        int run = 0;
        for (int i = 0; i < SCAN_NBLK; i++) { int c = sm[i]; sm[i] = run; run += c; }
        g_rowstart[N_NODES] = run;
    }
    __syncthreads();
    if (t < SCAN_NBLK) g_blockoff[t] = sm[t];
}

__global__ __launch_bounds__(SCAN_BLK) void scan3_kernel() {
    __shared__ int warp_s[32];
    int idx = blockIdx.x * SCAN_BLK + threadIdx.x;
    int wid = threadIdx.x >> 5, lane = threadIdx.x & 31;
    int c = (idx < N_NODES) ? g_indeg[idx] : 0;
    int v = c;
#pragma unroll
    for (int o = 1; o < 32; o <<= 1) {
        int u = __shfl_up_sync(0xffffffffu, v, o);
        if (lane >= o) v += u;
    }
    if (lane == 31) warp_s[wid] = v;
    __syncthreads();
    if (wid == 0) {
        int s = (lane < SCAN_BLK / 32) ? warp_s[lane] : 0;
#pragma unroll
        for (int o = 1; o < 32; o <<= 1) {
            int u = __shfl_up_sync(0xffffffffu, s, o);
            if (lane >= o) s += u;
        }
        if (lane < SCAN_BLK / 32) warp_s[lane] = s;
    }
    __syncthreads();
    int excl = v - c + (wid > 0 ? warp_s[wid - 1] : 0) + g_blockoff[blockIdx.x];
    if (idx < N_NODES) {
        g_rowstart[idx] = excl;
        g_pos[idx]      = excl;
        g_dinv[idx]     = rsqrtf((float)c + 1.0f);
        g_rcnt[idx]     = 1.0f / (float)max(c, 1);
    }
}

__global__ void scatter_kernel() {
    int e = blockIdx.x * blockDim.x + threadIdx.x;
    if (e < N_EDGES) {
        int d = g_dst[e];
        int p = atomicAdd(&g_pos[d], 1);
        g_csr[p] = g_src[e];
    }
}

// ---------------- GCN GEMM: A fp32 -> bf16 round; out bf16 (unchanged, hidden) -------
#define SMW 20
__global__ __launch_bounds__(256, 2) void gemm_gcn(
    const float* __restrict__ A,
    const uint32_t* __restrict__ Whi, const uint32_t* __restrict__ Wlo,
    __nv_bfloat16* __restrict__ outb, int M)
{
    __shared__ uint32_t sAh[128][SMW];
    __shared__ uint32_t sWhi[128][SMW], sWlo[128][SMW];

    const int t    = threadIdx.x;
    const int warp = t >> 5;
    const int lane = t & 31;
    const int wm   = warp >> 1;
    const int wn   = warp & 1;
    const int m0   = blockIdx.x * 128;
    const int r    = lane >> 2;
    const int kq   = lane & 3;

    float acc[2][8][4];
#pragma unroll
    for (int i = 0; i < 2; i++)
#pragma unroll
        for (int j = 0; j < 8; j++)
#pragma unroll
            for (int q = 0; q < 4; q++) acc[i][j][q] = 0.0f;

    for (int k0 = 0; k0 < 128; k0 += 32) {
#pragma unroll
        for (int i = 0; i < 4; i++) {
            int slot = t + i * 256;
            int row  = slot >> 3;
            int c4   = slot & 7;
            int ar   = m0 + row; if (ar >= M) ar = M - 1;
            float4 av = __ldg((const float4*)(A + (size_t)ar * 128 + k0 + c4 * 4));
            __nv_bfloat162 h0 = __floats2bfloat162_rn(av.x, av.y);
            __nv_bfloat162 h1 = __floats2bfloat162_rn(av.z, av.w);
            sAh[row][c4 * 2]     = *reinterpret_cast<uint32_t*>(&h0);
            sAh[row][c4 * 2 + 1] = *reinterpret_cast<uint32_t*>(&h1);
        }
        {
            int kb = k0 >> 1;
#pragma unroll
            for (int i = 0; i < 8; i++) {
                int idx = t + i * 256;
                int row = idx & 127;
                int w   = idx >> 7;
                sWhi[row][w] = __ldg(Whi + (kb + w) * 128 + row);
                sWlo[row][w] = __ldg(Wlo + (kb + w) * 128 + row);
            }
        }
        __syncthreads();

#pragma unroll
        for (int kk = 0; kk < 32; kk += 16) {
            const int kw = kk >> 1;
            uint32_t ah[2][4];
#pragma unroll
            for (int mt = 0; mt < 2; mt++) {
                int mr = wm * 32 + mt * 16;
                ah[mt][0] = sAh[mr + r][kw + kq];
                ah[mt][1] = sAh[mr + r + 8][kw + kq];
                ah[mt][2] = sAh[mr + r][kw + kq + 4];
                ah[mt][3] = sAh[mr + r + 8][kw + kq + 4];
            }
#pragma unroll
            for (int g = 0; g < 2; g++) {
                uint32_t bh[4][2], bl[4][2];
#pragma unroll
                for (int n2 = 0; n2 < 4; n2++) {
                    int nr = wn * 64 + g * 32 + n2 * 8 + r;
                    bh[n2][0] = sWhi[nr][kw + kq];
                    bh[n2][1] = sWhi[nr][kw + kq + 4];
                    bl[n2][0] = sWlo[nr][kw + kq];
                    bl[n2][1] = sWlo[nr][kw + kq + 4];
                }
#pragma unroll
                for (int mt = 0; mt < 2; mt++)
#pragma unroll
                    for (int n2 = 0; n2 < 4; n2++) {
                        float* c = acc[mt][g * 4 + n2];
                        mma_bf16(c, ah[mt], bh[n2]);
                        mma_bf16(c, ah[mt], bl[n2]);
                    }
            }
        }
        __syncthreads();
    }

#pragma unroll
    for (int mt = 0; mt < 2; mt++) {
#pragma unroll
        for (int nt = 0; nt < 8; nt++) {
            int gcol = wn * 64 + nt * 8 + kq * 2;
            int grow = m0 + wm * 32 + mt * 16 + r;
            if (grow < M)
                *(__nv_bfloat162*)(outb + (size_t)grow * 128 + gcol) =
                    __floats2bfloat162_rn(acc[mt][nt][0], acc[mt][nt][1]);
            int grow2 = grow + 8;
            if (grow2 < M)
                *(__nv_bfloat162*)(outb + (size_t)grow2 * 128 + gcol) =
                    __floats2bfloat162_rn(acc[mt][nt][2], acc[mt][nt][3]);
        }
    }
}

// ---------------- dual GEMM v2: resident W + double-buffered A + prefetch ----------
// out = A1@W1 + A2@W2 + bias (bf16 out). One __syncthreads per k-chunk.
__global__ __launch_bounds__(256, 2) void gemm_dual(
    const __nv_bfloat16* __restrict__ A1,
    const uint32_t* __restrict__ W1hi, const uint32_t* __restrict__ W1lo,
    const __nv_bfloat16* __restrict__ A2,
    const uint32_t* __restrict__ W2hi, const uint32_t* __restrict__ W2lo,
    const float* __restrict__ bias,
    __nv_bfloat16* __restrict__ outb, int M)
{
    extern __shared__ uint32_t ds[];
    uint32_t (*sWhi)[WF_STR] = (uint32_t(*)[WF_STR])ds;
    uint32_t (*sWlo)[WF_STR] = (uint32_t(*)[WF_STR])(ds + 128 * WF_STR);
    uint32_t (*sA0)[A_STR]   = (uint32_t(*)[A_STR])(ds + 2 * 128 * WF_STR);
    uint32_t (*sA1)[A_STR]   = (uint32_t(*)[A_STR])(ds + 2 * 128 * WF_STR + 128 * A_STR);

    const int t    = threadIdx.x;
    const int warp = t >> 5;
    const int lane = t & 31;
    const int wm   = warp >> 1;
    const int wn   = warp & 1;
    const int m0   = blockIdx.x * 128;
    const int r    = lane >> 2;
    const int kq   = lane & 3;

    // thread's A slot mapping (2 uint4 per thread per chunk)
    const int row0 = (t + 0)   >> 2, c160 = (t + 0)   & 3;
    const int row1 = (t + 256) >> 2, c161 = (t + 256) & 3;
    int ar0 = m0 + row0; if (ar0 >= M) ar0 = M - 1;
    int ar1 = m0 + row1; if (ar1 >= M) ar1 = M - 1;

    float acc[2][8][4];
#pragma unroll
    for (int i = 0; i < 2; i++)
#pragma unroll
        for (int j = 0; j < 8; j++)
#pragma unroll
            for (int q = 0; q < 4; q++) acc[i][j][q] = 0.0f;

#pragma unroll
    for (int pass = 0; pass < 2; pass++) {
        const __nv_bfloat16* A = pass ? A2 : A1;
        const uint32_t* Whi = pass ? W2hi : W1hi;
        const uint32_t* Wlo = pass ? W2lo : W1lo;

        // load full W (8192 u32 per array) + A chunk 0 into sA0
#pragma unroll
        for (int i = 0; i < 32; i++) {
            int idx = t + i * 256;
            int p = idx >> 7, rr = idx & 127;
            sWhi[rr][p] = __ldg(Whi + idx);
            sWlo[rr][p] = __ldg(Wlo + idx);
        }
        {
            uint4 v0 = __ldg((const uint4*)(A + (size_t)ar0 * 128) + c160);
            uint4 v1 = __ldg((const uint4*)(A + (size_t)ar1 * 128) + c161);
            *(uint4*)&sA0[row0][c160 * 4] = v0;
            *(uint4*)&sA1[0][0]; // no-op placeholder removed by compiler
            *(uint4*)&sA0[row1][c161 * 4] = v1;
        }
        __syncthreads();

#pragma unroll
        for (int c = 0; c < 4; c++) {
            // prefetch next A chunk (hidden behind MMAs below)
            uint4 p0, p1;
            if (c < 3) {
                int k0n = (c + 1) * 32;
                p0 = __ldg((const uint4*)(A + (size_t)ar0 * 128 + k0n) + c160);
                p1 = __ldg((const uint4*)(A + (size_t)ar1 * 128 + k0n) + c161);
            }

            uint32_t (*sA)[A_STR] = (c & 1) ? sA1 : sA0;
            const int base = c * 16;
#pragma unroll
            for (int kk = 0; kk < 32; kk += 16) {
                const int kw = kk >> 1;
                uint32_t ah[2][4];
#pragma unroll
                for (int mt = 0; mt < 2; mt++) {
                    int mr = wm * 32 + mt * 16;
                    ah[mt][0] = sA[mr + r][kw + kq];
                    ah[mt][1] = sA[mr + r + 8][kw + kq];
                    ah[mt][2] = sA[mr + r][kw + kq + 4];
                    ah[mt][3] = sA[mr + r + 8][kw + kq + 4];
                }
#pragma unroll
                for (int g = 0; g < 2; g++) {
                    uint32_t bh[4][2], bl[4][2];
#pragma unroll
                    for (int n2 = 0; n2 < 4; n2++) {
                        int nr = wn * 64 + g * 32 + n2 * 8 + r;
                        bh[n2][0] = sWhi[nr][base + kw + kq];
                        bh[n2][1] = sWhi[nr][base + kw + kq + 4];
                        bl[n2][0] = sWlo[nr][base + kw + kq];
                        bl[n2][1] = sWlo[nr][base + kw + kq + 4];
                    }
#pragma unroll
                    for (int mt = 0; mt < 2; mt++)
#pragma unroll
                        for (int n2 = 0; n2 < 4; n2++) {
                            float* cc = acc[mt][g * 4 + n2];
                            mma_bf16(cc, ah[mt], bh[n2]);
                            mma_bf16(cc, ah[mt], bl[n2]);
                        }
                }
            }

            // store prefetched chunk into the idle buffer (no one reads it)
            if (c < 3) {
                uint32_t (*sAn)[A_STR] = ((c + 1) & 1) ? sA1 : sA0;
                *(uint4*)&sAn[row0][c160 * 4] = p0;
                *(uint4*)&sAn[row1][c161 * 4] = p1;
            }
            __syncthreads();
        }
    }

#pragma unroll
    for (int mt = 0; mt < 2; mt++) {
#pragma unroll
        for (int nt = 0; nt < 8; nt++) {
            int gcol = wn * 64 + nt * 8 + kq * 2;
            float b0 = bias[gcol], b1 = bias[gcol + 1];
            int grow = m0 + wm * 32 + mt * 16 + r;
            if (grow < M)
                *(__nv_bfloat162*)(outb + (size_t)grow * 128 + gcol) =
                    __floats2bfloat162_rn(acc[mt][nt][0] + b0, acc[mt][nt][1] + b1);
            int grow2 = grow + 8;
            if (grow2 < M)
                *(__nv_bfloat162*)(outb + (size_t)grow2 * 128 + gcol) =
                    __floats2bfloat162_rn(acc[mt][nt][2] + b0, acc[mt][nt][3] + b1);
        }
    }
}

// ---------------- CSR gathers (bf16 in, bf16 out, fp32 accumulate) ----------------
__global__ __launch_bounds__(256) void gcn_gather_kernel(
    const __nv_bfloat16* __restrict__ xwb, __nv_bfloat16* __restrict__ outb,
    const float* __restrict__ bias)
{
    int w = (blockIdx.x * blockDim.x + threadIdx.x) >> 5;
    int lane = threadIdx.x & 31;
    if (w >= N_NODES) return;
    int beg = g_rowstart[w], end = g_rowstart[w + 1];
    float dn = g_dinv[w];
    float4 acc = make_float4(0.f, 0.f, 0.f, 0.f);
    for (int b = beg; b < end; b += 32) {
        int nb = min(32, end - b);
        int s_l = 0; float d_l = 0.f;
        if (b + lane < end) { s_l = g_csr[b + lane]; d_l = g_dinv[s_l]; }
        for (int j = 0; j < nb; j++) {
            int   s  = __shfl_sync(0xffffffffu, s_l, j);
            float nm = __shfl_sync(0xffffffffu, d_l, j) * dn;
            acc_bf16row(acc, xwb, s, lane, nm);
        }
    }
    float4 bv = *(const float4*)(bias + lane * 4);
    acc.x += bv.x; acc.y += bv.y; acc.z += bv.z; acc.w += bv.w;
    acc_bf16row(acc, xwb, w, lane, dn * dn);
    store_bf16row(outb, w, lane, acc);
}

__global__ __launch_bounds__(256) void sage_gather_kernel(
    const __nv_bfloat16* __restrict__ hb, __nv_bfloat16* __restrict__ outb)
{
    int w = (blockIdx.x * blockDim.x + threadIdx.x) >> 5;
    int lane = threadIdx.x & 31;
    if (w >= N_NODES) return;
    int beg = g_rowstart[w], end = g_rowstart[w + 1];
    float4 acc = make_float4(0.f, 0.f, 0.f, 0.f);
    for (int b = beg; b < end; b += 32) {
        int nb = min(32, end - b);
        int s_l = 0;
        if (b + lane < end) s_l = g_csr[b + lane];
        for (int j = 0; j < nb; j++) {
            int s = __shfl_sync(0xffffffffu, s_l, j);
            acc_bf16row(acc, hb, s, lane, 1.0f);
        }
    }
    float rc = g_rcnt[w];
    acc.x *= rc; acc.y *= rc; acc.z *= rc; acc.w *= rc;
    store_bf16row(outb, w, lane, acc);
}

// ---------------- pooling (bf16 input) ----------------
__device__ __forceinline__ int lower_bound_batch(int val) {
    int lo = 0, hi = N_NODES;
    while (lo < hi) {
        int mid = (lo + hi) >> 1;
        if (g_batch[mid] < val) lo = mid + 1; else hi = mid;
    }
    return lo;
}

__global__ void pool_kernel(const __nv_bfloat16* __restrict__ h) {
    int g = blockIdx.x;
    int part = blockIdx.y;
    int f = threadIdx.x;
    int lo = lower_bound_batch(g);
    int hi = lower_bound_batch(g + 1);
    float acc = 0.f;
    for (int n = lo + part; n < hi; n += 8)
        acc += __bfloat162float(h[(size_t)n * 128 + f]);
    atomicAdd(&g_pool[g * 128 + f], acc);
    if (part == 0 && f == 0) g_gcnt[g] = max(hi - lo, 1);
}

// ---------------- classifier MLP + softmax ----------------
__global__ void mlp_kernel(
    const float* __restrict__ w0, const float* __restrict__ b0,
    const float* __restrict__ w1, const float* __restrict__ b1,
    const float* __restrict__ w2, const float* __restrict__ b2,
    const float* __restrict__ w3, const float* __restrict__ b3,
    const float* __restrict__ bn0g, const float* __restrict__ bn0b,
    const float* __restrict__ bn1g, const float* __restrict__ bn1b,
    const float* __restrict__ bn2g, const float* __restrict__ bn2b,
    float* __restrict__ out)
{
    __shared__ float sin_[128], h0[200], h1[100], h2[50], lg[10];
    int g = blockIdx.x, t = threadIdx.x;
    if (t < 128) sin_[t] = g_pool[g * 128 + t] / (float)g_gcnt[g];
    __syncthreads();
    const float bnc = rsqrtf(1.0f + 1e-5f);
    if (t < 200) {
        float s = b0[t];
        const float* wr = w0 + (size_t)t * 128;
#pragma unroll 4
        for (int k = 0; k < 128; k++) s += wr[k] * sin_[k];
        h0[t] = tanhf(s * bn0g[t] * bnc + bn0b[t]);
    }
    __syncthreads();
    if (t < 100) {
        float s = b1[t];
        const float* wr = w1 + (size_t)t * 200;
#pragma unroll 4
        for (int k = 0; k < 200; k++) s += wr[k] * h0[k];
        h1[t] = tanhf(s * bn1g[t] * bnc + bn1b[t]);
    }
    __syncthreads();
    if (t < 50) {
        float s = b2[t];
        const float* wr = w2 + (size_t)t * 100;
#pragma unroll 4
        for (int k = 0; k < 100; k++) s += wr[k] * h1[k];
        h2[t] = tanhf(s * bn2g[t] * bnc + bn2b[t]);
    }
    __syncthreads();
    if (t < 10) {
        float s = b3[t];
        const float* wr = w3 + (size_t)t * 50;
#pragma unroll
        for (int k = 0; k < 50; k++) s += wr[k] * h2[k];
        lg[t] = s;
    }
    __syncthreads();
    if (t == 0) {
        float m = lg[0];
        for (int c = 1; c < N_CLASSES; c++) m = fmaxf(m, lg[c]);
        float e[N_CLASSES];
        float sum = 0.f;
        for (int c = 0; c < N_CLASSES; c++) { e[c] = expf(lg[c] - m); sum += e[c]; }
        float inv = 1.0f / sum;
        for (int c = 0; c < N_CLASSES; c++) out[g * N_CLASSES + c] = e[c] * inv;
    }
}

// ---------------- launch ----------------
extern "C" void kernel_launch(void* const* d_in, const int* in_sizes, int n_in,
                              void* d_out, int out_size)
{
    const float* x       = (const float*)d_in[0];
    const void*  ei      = d_in[1];
    const void*  bt      = d_in[2];
    const float* gcn_w   = (const float*)d_in[3];
    const float* gcn_b   = (const float*)d_in[4];
    const float* s1_wl   = (const float*)d_in[5];
    const float* s1_bl   = (const float*)d_in[6];
    const float* s1_wr   = (const float*)d_in[7];
    const float* s2_wl   = (const float*)d_in[8];
    const float* s2_bl   = (const float*)d_in[9];
    const float* s2_wr   = (const float*)d_in[10];
    const float* c_w0 = (const float*)d_in[11]; const float* c_b0 = (const float*)d_in[12];
    const float* c_w1 = (const float*)d_in[13]; const float* c_b1 = (const float*)d_in[14];
    const float* c_w2 = (const float*)d_in[15]; const float* c_b2 = (const float*)d_in[16];
    const float* c_w3 = (const float*)d_in[17]; const float* c_b3 = (const float*)d_in[18];
    const float* bn0g = (const float*)d_in[19]; const float* bn0b = (const float*)d_in[20];
    const float* bn1g = (const float*)d_in[21]; const float* bn1b = (const float*)d_in[22];
    const float* bn2g = (const float*)d_in[23]; const float* bn2b = (const float*)d_in[24];
    float* out = (float*)d_out;

    __nv_bfloat16 *B1, *B2, *B3, *Bagg;
    uint32_t *Wg_hi, *Wg_lo, *W1l_hi, *W1l_lo, *W1r_hi, *W1r_lo;
    uint32_t *W2l_hi, *W2l_lo, *W2r_hi, *W2r_lo;
    cudaGetSymbolAddress((void**)&B1, g_B1);
    cudaGetSymbolAddress((void**)&B2, g_B2);
    cudaGetSymbolAddress((void**)&B3, g_B3);
    cudaGetSymbolAddress((void**)&Bagg, g_Bagg);
    cudaGetSymbolAddress((void**)&Wg_hi, g_Wg_hi);   cudaGetSymbolAddress((void**)&Wg_lo, g_Wg_lo);
    cudaGetSymbolAddress((void**)&W1l_hi, g_W1l_hi); cudaGetSymbolAddress((void**)&W1l_lo, g_W1l_lo);
    cudaGetSymbolAddress((void**)&W1r_hi, g_W1r_hi); cudaGetSymbolAddress((void**)&W1r_lo, g_W1r_lo);
    cudaGetSymbolAddress((void**)&W2l_hi, g_W2l_hi); cudaGetSymbolAddress((void**)&W2l_lo, g_W2l_lo);
    cudaGetSymbolAddress((void**)&W2r_hi, g_W2r_hi); cudaGetSymbolAddress((void**)&W2r_lo, g_W2r_lo);

    static cudaStream_t s_side = nullptr;
    static cudaEvent_t  s_fork = nullptr, s_join = nullptr;
    if (s_side == nullptr) {
        cudaStreamCreateWithFlags(&s_side, cudaStreamNonBlocking);
        cudaEventCreateWithFlags(&s_fork, cudaEventDisableTiming);
        cudaEventCreateWithFlags(&s_join, cudaEventDisableTiming);
        cudaFuncSetAttribute(gemm_dual,
                             cudaFuncAttributeMaxDynamicSharedMemorySize, GEMM_SMEM);
    }

    const int TB = 256;
    const int nodeBlocks   = (N_NODES + TB - 1) / TB;
    const int edgeBlocks   = (N_EDGES + TB - 1) / TB;
    const int gatherBlocks = (N_NODES + 7) / 8;
    const int gemmBlocks   = (N_NODES + 127) / 128;

    // fork at t=0: side stream does prepack + GCN GEMM, hidden under CSR build
    cudaEventRecord(s_fork, 0);
    cudaStreamWaitEvent(s_side, s_fork, 0);
    prepack_all<<<160, 256, 0, s_side>>>(gcn_w, s1_wl, s1_wr, s2_wl, s2_wr);
    gemm_gcn<<<gemmBlocks, 256, 0, s_side>>>(x, Wg_hi, Wg_lo, B1, N_NODES);

    // main stream: index prep + CSR build
    detect_kernel<<<1, 256>>>(ei);
    zero_kernel<<<nodeBlocks, TB>>>();
    convert_hist_kernel<<<edgeBlocks, TB>>>(ei, bt);
    scan1_kernel<<<SCAN_NBLK, SCAN_BLK>>>();
    scan2_kernel<<<1, 128>>>();
    scan3_kernel<<<SCAN_NBLK, SCAN_BLK>>>();
    scatter_kernel<<<edgeBlocks, TB>>>();

    cudaEventRecord(s_join, s_side);
    cudaStreamWaitEvent(0, s_join, 0);

    // GCN aggregate: B2 = norm-agg(B1) + self(B1)*dinv^2 + bias
    gcn_gather_kernel<<<gatherBlocks, 256>>>(B1, B2, gcn_b);

    // SAGE1: Bagg = mean-agg(B2); B3 = Bagg@W1l + bl + B2@W1r
    sage_gather_kernel<<<gatherBlocks, 256>>>(B2, Bagg);
    gemm_dual<<<gemmBlocks, 256, GEMM_SMEM>>>(Bagg, W1l_hi, W1l_lo, B2, W1r_hi, W1r_lo,
                                              s1_bl, B3, N_NODES);

    // SAGE2: Bagg = mean-agg(B3); B1 = Bagg@W2l + bl + B3@W2r
    sage_gather_kernel<<<gatherBlocks, 256>>>(B3, Bagg);
    gemm_dual<<<gemmBlocks, 256, GEMM_SMEM>>>(Bagg, W2l_hi, W2l_lo, B3, W2r_hi, W2r_lo,
                                              s2_bl, B1, N_NODES);

    // pool + classifier
    dim3 pg(N_GRAPHS, 8);
    pool_kernel<<<pg, 128>>>(B1);
    mlp_kernel<<<N_GRAPHS, 256>>>(c_w0, c_b0, c_w1, c_b1, c_w2, c_b2, c_w3, c_b3,
                                  bn0g, bn0b, bn1g, bn1b, bn2g, bn2b, out);
}

// round 14
// speedup vs baseline: 1.3642x; 1.0073x over previous
#include <cuda_runtime.h>
#include <cuda_bf16.h>
#include <math.h>
#include <stdint.h>

// ---------------- constants ----------------
#define N_NODES  100000
#define N_EDGES  1600000
#define FEAT     128
#define N_GRAPHS 64
#define N_CLASSES 10

#define SCAN_BLK   1024
#define SCAN_NBLK  ((N_NODES + SCAN_BLK - 1) / SCAN_BLK)   // 98

// GEMM dynamic smem: full W (hi+lo, 128x68 u32 each) + double-buffered A (2x128x20)
#define WF_STR 68
#define A_STR  20
#define GEMM_SMEM ((2 * 128 * WF_STR + 2 * 128 * A_STR) * 4)   // 90112 B

// ---------------- device scratch ----------------
__device__ __nv_bfloat16 g_B1[(size_t)N_NODES * FEAT];   // gcn gemm out; later final out
__device__ __nv_bfloat16 g_B2[(size_t)N_NODES * FEAT];   // gcn layer out (h1)
__device__ __nv_bfloat16 g_B3[(size_t)N_NODES * FEAT];   // sage1 out (h2)
__device__ __nv_bfloat16 g_Bagg[(size_t)N_NODES * FEAT]; // aggregation scratch

// pre-split weights, k-major: [pair 0..63][row 0..127]
__device__ uint32_t g_Wg_hi[64 * 128],  g_Wg_lo[64 * 128];
__device__ uint32_t g_W1l_hi[64 * 128], g_W1l_lo[64 * 128];
__device__ uint32_t g_W1r_hi[64 * 128], g_W1r_lo[64 * 128];
__device__ uint32_t g_W2l_hi[64 * 128], g_W2l_lo[64 * 128];
__device__ uint32_t g_W2r_hi[64 * 128], g_W2r_lo[64 * 128];

__device__ int   g_src[N_EDGES];
__device__ int   g_dst[N_EDGES];
__device__ int   g_csr[N_EDGES];
__device__ int   g_batch[N_NODES];
__device__ int   g_indeg[N_NODES];
__device__ int   g_rowstart[N_NODES + 1];
__device__ int   g_pos[N_NODES];
__device__ float g_dinv[N_NODES];
__device__ float g_rcnt[N_NODES];
__device__ float g_pool[N_GRAPHS * FEAT];
__device__ int   g_gcnt[N_GRAPHS];
__device__ int   g_blocksum[SCAN_NBLK];
__device__ int   g_blockoff[SCAN_NBLK];
__device__ int   g_is64;

// ---------------- helpers ----------------
__device__ __forceinline__ void split2(float x, float y, uint32_t& hi, uint32_t& lo) {
    __nv_bfloat162 h = __floats2bfloat162_rn(x, y);
    float2 hf = __bfloat1622float2(h);
    __nv_bfloat162 l = __floats2bfloat162_rn(x - hf.x, y - hf.y);
    hi = *reinterpret_cast<uint32_t*>(&h);
    lo = *reinterpret_cast<uint32_t*>(&l);
}

__device__ __forceinline__ void mma_bf16(float* c, const uint32_t* a, const uint32_t* b) {
    asm volatile(
        "mma.sync.aligned.m16n8k16.row.col.f32.bf16.bf16.f32 "
        "{%0,%1,%2,%3}, {%4,%5,%6,%7}, {%8,%9}, {%0,%1,%2,%3};\n"
        : "+f"(c[0]), "+f"(c[1]), "+f"(c[2]), "+f"(c[3])
        : "r"(a[0]), "r"(a[1]), "r"(a[2]), "r"(a[3]), "r"(b[0]), "r"(b[1]));
}

__device__ __forceinline__ void acc_bf16row(float4& acc, const __nv_bfloat16* __restrict__ hb,
                                            int s, int lane, float nm) {
    uint2 raw = __ldg((const uint2*)(hb + (size_t)s * 128) + lane);
    float2 p0 = __bfloat1622float2(*reinterpret_cast<__nv_bfloat162*>(&raw.x));
    float2 p1 = __bfloat1622float2(*reinterpret_cast<__nv_bfloat162*>(&raw.y));
    acc.x += p0.x * nm; acc.y += p0.y * nm;
    acc.z += p1.x * nm; acc.w += p1.y * nm;
}

__device__ __forceinline__ void store_bf16row(__nv_bfloat16* __restrict__ outb,
                                              int w, int lane, const float4& acc) {
    uint2 ob;
    __nv_bfloat162 q0 = __floats2bfloat162_rn(acc.x, acc.y);
    __nv_bfloat162 q1 = __floats2bfloat162_rn(acc.z, acc.w);
    ob.x = *reinterpret_cast<uint32_t*>(&q0);
    ob.y = *reinterpret_cast<uint32_t*>(&q1);
    *((uint2*)(outb + (size_t)w * 128) + lane) = ob;
}

// ---------------- merged weight prepack ----------------
__global__ void prepack_all(const float* __restrict__ Wg,
                            const float* __restrict__ W1l, const float* __restrict__ W1r,
                            const float* __restrict__ W2l, const float* __restrict__ W2r)
{
    int widx = blockIdx.x >> 5;
    int idx  = (blockIdx.x & 31) * 256 + threadIdx.x;
    const float* W; uint32_t *hi, *lo;
    switch (widx) {
        case 0: W = Wg;  hi = g_Wg_hi;  lo = g_Wg_lo;  break;
        case 1: W = W1l; hi = g_W1l_hi; lo = g_W1l_lo; break;
        case 2: W = W1r; hi = g_W1r_hi; lo = g_W1r_lo; break;
        case 3: W = W2l; hi = g_W2l_hi; lo = g_W2l_lo; break;
        default:W = W2r; hi = g_W2r_hi; lo = g_W2r_lo; break;
    }
    int p = idx >> 7;
    int r = idx & 127;
    float x = W[r * 128 + p * 2];
    float y = W[r * 128 + p * 2 + 1];
    uint32_t h, l;
    split2(x, y, h, l);
    hi[p * 128 + r] = h;
    lo[p * 128 + r] = l;
}

// ---------------- index dtype detection ----------------
__global__ void detect_kernel(const void* ei) {
    const unsigned long long* p = (const unsigned long long*)ei;
    unsigned long long v = p[threadIdx.x];
    unsigned int hi = (unsigned int)(v >> 32);
    unsigned int any = __ballot_sync(0xffffffffu, hi != 0u);
    __shared__ int s_any;
    if (threadIdx.x == 0) s_any = 0;
    __syncthreads();
    if (any != 0u && (threadIdx.x & 31) == 0) atomicOr(&s_any, 1);
    __syncthreads();
    if (threadIdx.x == 0) g_is64 = s_any ? 0 : 1;
}

__global__ void zero_kernel() {
    int i = blockIdx.x * blockDim.x + threadIdx.x;
    if (i < N_NODES) g_indeg[i] = 0;
    if (i < N_GRAPHS * FEAT) g_pool[i] = 0.0f;
}

__global__ void convert_hist_kernel(const void* ei, const void* bt) {
    int i = blockIdx.x * blockDim.x + threadIdx.x;
    const int is64 = g_is64;
    if (i < N_EDGES) {
        int s, d;
        if (is64) {
            s = (int)((const long long*)ei)[i];
            d = (int)((const long long*)ei)[(size_t)N_EDGES + i];
        } else {
            s = ((const int*)ei)[i];
            d = ((const int*)ei)[N_EDGES + i];
        }
        g_src[i] = s;
        g_dst[i] = d;
        atomicAdd(&g_indeg[d], 1);
    }
    if (i < N_NODES) {
        g_batch[i] = is64 ? (int)((const long long*)bt)[i] : ((const int*)bt)[i];
    }
}

// ---------------- 3-phase multi-block scan ----------------
__global__ __launch_bounds__(SCAN_BLK) void scan1_kernel() {
    __shared__ int warp_s[32];
    int idx = blockIdx.x * SCAN_BLK + threadIdx.x;
    int v = (idx < N_NODES) ? g_indeg[idx] : 0;
#pragma unroll
    for (int o = 16; o > 0; o >>= 1) v += __shfl_down_sync(0xffffffffu, v, o);
    int wid = threadIdx.x >> 5, lane = threadIdx.x & 31;
    if (lane == 0) warp_s[wid] = v;
    __syncthreads();
    if (wid == 0) {
        int s = (lane < SCAN_BLK / 32) ? warp_s[lane] : 0;
#pragma unroll
        for (int o = 16; o > 0; o >>= 1) s += __shfl_down_sync(0xffffffffu, s, o);
        if (lane == 0) g_blocksum[blockIdx.x] = s;
    }
}

__global__ void scan2_kernel() {
    __shared__ int sm[SCAN_NBLK];
    int t = threadIdx.x;
    int v = (t < SCAN_NBLK) ? g_blocksum[t] : 0;
    if (t < SCAN_NBLK) sm[t] = v;
    __syncthreads();
    if (t == 0) {
        int run = 0;
        for (int i = 0; i < SCAN_NBLK; i++) { int c = sm[i]; sm[i] = run; run += c; }
        g_rowstart[N_NODES] = run;
    }
    __syncthreads();
    if (t < SCAN_NBLK) g_blockoff[t] = sm[t];
}

__global__ __launch_bounds__(SCAN_BLK) void scan3_kernel() {
    __shared__ int warp_s[32];
    int idx = blockIdx.x * SCAN_BLK + threadIdx.x;
    int wid = threadIdx.x >> 5, lane = threadIdx.x & 31;
    int c = (idx < N_NODES) ? g_indeg[idx] : 0;
    int v = c;
#pragma unroll
    for (int o = 1; o < 32; o <<= 1) {
        int u = __shfl_up_sync(0xffffffffu, v, o);
        if (lane >= o) v += u;
    }
    if (lane == 31) warp_s[wid] = v;
    __syncthreads();
    if (wid == 0) {
        int s = (lane < SCAN_BLK / 32) ? warp_s[lane] : 0;
#pragma unroll
        for (int o = 1; o < 32; o <<= 1) {
            int u = __shfl_up_sync(0xffffffffu, s, o);
            if (lane >= o) s += u;
        }
        if (lane < SCAN_BLK / 32) warp_s[lane] = s;
    }
    __syncthreads();
    int excl = v - c + (wid > 0 ? warp_s[wid - 1] : 0) + g_blockoff[blockIdx.x];
    if (idx < N_NODES) {
        g_rowstart[idx] = excl;
        g_pos[idx]      = excl;
        g_dinv[idx]     = rsqrtf((float)c + 1.0f);
        g_rcnt[idx]     = 1.0f / (float)max(c, 1);
    }
}

__global__ void scatter_kernel() {
    int e = blockIdx.x * blockDim.x + threadIdx.x;
    if (e < N_EDGES) {
        int d = g_dst[e];
        int p = atomicAdd(&g_pos[d], 1);
        g_csr[p] = g_src[e];
    }
}

// ---------------- GCN GEMM v2: resident W + double-buffered fp32 A + prefetch -------
__global__ __launch_bounds__(256, 2) void gemm_gcn(
    const float* __restrict__ A,
    const uint32_t* __restrict__ Whi, const uint32_t* __restrict__ Wlo,
    __nv_bfloat16* __restrict__ outb, int M)
{
    extern __shared__ uint32_t ds[];
    uint32_t (*sWhi)[WF_STR] = (uint32_t(*)[WF_STR])ds;
    uint32_t (*sWlo)[WF_STR] = (uint32_t(*)[WF_STR])(ds + 128 * WF_STR);
    uint32_t (*sA0)[A_STR]   = (uint32_t(*)[A_STR])(ds + 2 * 128 * WF_STR);
    uint32_t (*sA1)[A_STR]   = (uint32_t(*)[A_STR])(ds + 2 * 128 * WF_STR + 128 * A_STR);

    const int t    = threadIdx.x;
    const int warp = t >> 5;
    const int lane = t & 31;
    const int wm   = warp >> 1;
    const int wn   = warp & 1;
    const int m0   = blockIdx.x * 128;
    const int r    = lane >> 2;
    const int kq   = lane & 3;

    // A slot mapping: 4 float4 per thread per chunk (slots t, t+256, t+512, t+768)
    int rows[4], c4s[4], ars[4];
#pragma unroll
    for (int i = 0; i < 4; i++) {
        int slot = t + i * 256;
        rows[i] = slot >> 3;
        c4s[i]  = slot & 7;
        int ar = m0 + rows[i]; if (ar >= M) ar = M - 1;
        ars[i] = ar;
    }

    float acc[2][8][4];
#pragma unroll
    for (int i = 0; i < 2; i++)
#pragma unroll
        for (int j = 0; j < 8; j++)
#pragma unroll
            for (int q = 0; q < 4; q++) acc[i][j][q] = 0.0f;

    // load full W + A chunk 0
#pragma unroll
    for (int i = 0; i < 32; i++) {
        int idx = t + i * 256;
        int p = idx >> 7, rr = idx & 127;
        sWhi[rr][p] = __ldg(Whi + idx);
        sWlo[rr][p] = __ldg(Wlo + idx);
    }
#pragma unroll
    for (int i = 0; i < 4; i++) {
        float4 av = __ldg((const float4*)(A + (size_t)ars[i] * 128) + c4s[i]);
        __nv_bfloat162 h0 = __floats2bfloat162_rn(av.x, av.y);
        __nv_bfloat162 h1 = __floats2bfloat162_rn(av.z, av.w);
        sA0[rows[i]][c4s[i] * 2]     = *reinterpret_cast<uint32_t*>(&h0);
        sA0[rows[i]][c4s[i] * 2 + 1] = *reinterpret_cast<uint32_t*>(&h1);
    }
    __syncthreads();

#pragma unroll
    for (int c = 0; c < 4; c++) {
        // prefetch next chunk fp32 (hidden behind MMAs)
        float4 pf[4];
        if (c < 3) {
            int k0n = (c + 1) * 32;
#pragma unroll
            for (int i = 0; i < 4; i++)
                pf[i] = __ldg((const float4*)(A + (size_t)ars[i] * 128 + k0n) + c4s[i]);
        }

        uint32_t (*sA)[A_STR] = (c & 1) ? sA1 : sA0;
        const int base = c * 16;
#pragma unroll
        for (int kk = 0; kk < 32; kk += 16) {
            const int kw = kk >> 1;
            uint32_t ah[2][4];
#pragma unroll
            for (int mt = 0; mt < 2; mt++) {
                int mr = wm * 32 + mt * 16;
                ah[mt][0] = sA[mr + r][kw + kq];
                ah[mt][1] = sA[mr + r + 8][kw + kq];
                ah[mt][2] = sA[mr + r][kw + kq + 4];
                ah[mt][3] = sA[mr + r + 8][kw + kq + 4];
            }
#pragma unroll
            for (int g = 0; g < 2; g++) {
                uint32_t bh[4][2], bl[4][2];
#pragma unroll
                for (int n2 = 0; n2 < 4; n2++) {
                    int nr = wn * 64 + g * 32 + n2 * 8 + r;
                    bh[n2][0] = sWhi[nr][base + kw + kq];
                    bh[n2][1] = sWhi[nr][base + kw + kq + 4];
                    bl[n2][0] = sWlo[nr][base + kw + kq];
                    bl[n2][1] = sWlo[nr][base + kw + kq + 4];
                }
#pragma unroll
                for (int mt = 0; mt < 2; mt++)
#pragma unroll
                    for (int n2 = 0; n2 < 4; n2++) {
                        float* cc = acc[mt][g * 4 + n2];
                        mma_bf16(cc, ah[mt], bh[n2]);
                        mma_bf16(cc, ah[mt], bl[n2]);
                    }
            }
        }

        if (c < 3) {
            uint32_t (*sAn)[A_STR] = ((c + 1) & 1) ? sA1 : sA0;
#pragma unroll
            for (int i = 0; i < 4; i++) {
                __nv_bfloat162 h0 = __floats2bfloat162_rn(pf[i].x, pf[i].y);
                __nv_bfloat162 h1 = __floats2bfloat162_rn(pf[i].z, pf[i].w);
                sAn[rows[i]][c4s[i] * 2]     = *reinterpret_cast<uint32_t*>(&h0);
                sAn[rows[i]][c4s[i] * 2 + 1] = *reinterpret_cast<uint32_t*>(&h1);
            }
        }
        __syncthreads();
    }

#pragma unroll
    for (int mt = 0; mt < 2; mt++) {
#pragma unroll
        for (int nt = 0; nt < 8; nt++) {
            int gcol = wn * 64 + nt * 8 + kq * 2;
            int grow = m0 + wm * 32 + mt * 16 + r;
            if (grow < M)
                *(__nv_bfloat162*)(outb + (size_t)grow * 128 + gcol) =
                    __floats2bfloat162_rn(acc[mt][nt][0], acc[mt][nt][1]);
            int grow2 = grow + 8;
            if (grow2 < M)
                *(__nv_bfloat162*)(outb + (size_t)grow2 * 128 + gcol) =
                    __floats2bfloat162_rn(acc[mt][nt][2], acc[mt][nt][3]);
        }
    }
}

// ---------------- dual GEMM v2: resident W + double-buffered A + prefetch ----------
__global__ __launch_bounds__(256, 2) void gemm_dual(
    const __nv_bfloat16* __restrict__ A1,
    const uint32_t* __restrict__ W1hi, const uint32_t* __restrict__ W1lo,
    const __nv_bfloat16* __restrict__ A2,
    const uint32_t* __restrict__ W2hi, const uint32_t* __restrict__ W2lo,
    const float* __restrict__ bias,
    __nv_bfloat16* __restrict__ outb, int M)
{
    extern __shared__ uint32_t ds[];
    uint32_t (*sWhi)[WF_STR] = (uint32_t(*)[WF_STR])ds;
    uint32_t (*sWlo)[WF_STR] = (uint32_t(*)[WF_STR])(ds + 128 * WF_STR);
    uint32_t (*sA0)[A_STR]   = (uint32_t(*)[A_STR])(ds + 2 * 128 * WF_STR);
    uint32_t (*sA1)[A_STR]   = (uint32_t(*)[A_STR])(ds + 2 * 128 * WF_STR + 128 * A_STR);

    const int t    = threadIdx.x;
    const int warp = t >> 5;
    const int lane = t & 31;
    const int wm   = warp >> 1;
    const int wn   = warp & 1;
    const int m0   = blockIdx.x * 128;
    const int r    = lane >> 2;
    const int kq   = lane & 3;

    const int row0 = (t + 0)   >> 2, c160 = (t + 0)   & 3;
    const int row1 = (t + 256) >> 2, c161 = (t + 256) & 3;
    int ar0 = m0 + row0; if (ar0 >= M) ar0 = M - 1;
    int ar1 = m0 + row1; if (ar1 >= M) ar1 = M - 1;

    float acc[2][8][4];
#pragma unroll
    for (int i = 0; i < 2; i++)
#pragma unroll
        for (int j = 0; j < 8; j++)
#pragma unroll
            for (int q = 0; q < 4; q++) acc[i][j][q] = 0.0f;

#pragma unroll
    for (int pass = 0; pass < 2; pass++) {
        const __nv_bfloat16* A = pass ? A2 : A1;
        const uint32_t* Whi = pass ? W2hi : W1hi;
        const uint32_t* Wlo = pass ? W2lo : W1lo;

#pragma unroll
        for (int i = 0; i < 32; i++) {
            int idx = t + i * 256;
            int p = idx >> 7, rr = idx & 127;
            sWhi[rr][p] = __ldg(Whi + idx);
            sWlo[rr][p] = __ldg(Wlo + idx);
        }
        {
            uint4 v0 = __ldg((const uint4*)(A + (size_t)ar0 * 128) + c160);
            uint4 v1 = __ldg((const uint4*)(A + (size_t)ar1 * 128) + c161);
            *(uint4*)&sA0[row0][c160 * 4] = v0;
            *(uint4*)&sA0[row1][c161 * 4] = v1;
        }
        __syncthreads();

#pragma unroll
        for (int c = 0; c < 4; c++) {
            uint4 p0, p1;
            if (c < 3) {
                int k0n = (c + 1) * 32;
                p0 = __ldg((const uint4*)(A + (size_t)ar0 * 128 + k0n) + c160);
                p1 = __ldg((const uint4*)(A + (size_t)ar1 * 128 + k0n) + c161);
            }

            uint32_t (*sA)[A_STR] = (c & 1) ? sA1 : sA0;
            const int base = c * 16;
#pragma unroll
            for (int kk = 0; kk < 32; kk += 16) {
                const int kw = kk >> 1;
                uint32_t ah[2][4];
#pragma unroll
                for (int mt = 0; mt < 2; mt++) {
                    int mr = wm * 32 + mt * 16;
                    ah[mt][0] = sA[mr + r][kw + kq];
                    ah[mt][1] = sA[mr + r + 8][kw + kq];
                    ah[mt][2] = sA[mr + r][kw + kq + 4];
                    ah[mt][3] = sA[mr + r + 8][kw + kq + 4];
                }
#pragma unroll
                for (int g = 0; g < 2; g++) {
                    uint32_t bh[4][2], bl[4][2];
#pragma unroll
                    for (int n2 = 0; n2 < 4; n2++) {
                        int nr = wn * 64 + g * 32 + n2 * 8 + r;
                        bh[n2][0] = sWhi[nr][base + kw + kq];
                        bh[n2][1] = sWhi[nr][base + kw + kq + 4];
                        bl[n2][0] = sWlo[nr][base + kw + kq];
                        bl[n2][1] = sWlo[nr][base + kw + kq + 4];
                    }
#pragma unroll
                    for (int mt = 0; mt < 2; mt++)
#pragma unroll
                        for (int n2 = 0; n2 < 4; n2++) {
                            float* cc = acc[mt][g * 4 + n2];
                            mma_bf16(cc, ah[mt], bh[n2]);
                            mma_bf16(cc, ah[mt], bl[n2]);
                        }
                }
            }

            if (c < 3) {
                uint32_t (*sAn)[A_STR] = ((c + 1) & 1) ? sA1 : sA0;
                *(uint4*)&sAn[row0][c160 * 4] = p0;
                *(uint4*)&sAn[row1][c161 * 4] = p1;
            }
            __syncthreads();
        }
    }

#pragma unroll
    for (int mt = 0; mt < 2; mt++) {
#pragma unroll
        for (int nt = 0; nt < 8; nt++) {
            int gcol = wn * 64 + nt * 8 + kq * 2;
            float b0 = bias[gcol], b1 = bias[gcol + 1];
            int grow = m0 + wm * 32 + mt * 16 + r;
            if (grow < M)
                *(__nv_bfloat162*)(outb + (size_t)grow * 128 + gcol) =
                    __floats2bfloat162_rn(acc[mt][nt][0] + b0, acc[mt][nt][1] + b1);
            int grow2 = grow + 8;
            if (grow2 < M)
                *(__nv_bfloat162*)(outb + (size_t)grow2 * 128 + gcol) =
                    __floats2bfloat162_rn(acc[mt][nt][2] + b0, acc[mt][nt][3] + b1);
        }
    }
}

// ---------------- CSR gathers (bf16 in, bf16 out, fp32 accumulate) ----------------
__global__ __launch_bounds__(256) void gcn_gather_kernel(
    const __nv_bfloat16* __restrict__ xwb, __nv_bfloat16* __restrict__ outb,
    const float* __restrict__ bias)
{
    int w = (blockIdx.x * blockDim.x + threadIdx.x) >> 5;
    int lane = threadIdx.x & 31;
    if (w >= N_NODES) return;
    int beg = g_rowstart[w], end = g_rowstart[w + 1];
    float dn = g_dinv[w];
    float4 acc = make_float4(0.f, 0.f, 0.f, 0.f);
    for (int b = beg; b < end; b += 32) {
        int nb = min(32, end - b);
        int s_l = 0; float d_l = 0.f;
        if (b + lane < end) { s_l = g_csr[b + lane]; d_l = g_dinv[s_l]; }
        for (int j = 0; j < nb; j++) {
            int   s  = __shfl_sync(0xffffffffu, s_l, j);
            float nm = __shfl_sync(0xffffffffu, d_l, j) * dn;
            acc_bf16row(acc, xwb, s, lane, nm);
        }
    }
    float4 bv = *(const float4*)(bias + lane * 4);
    acc.x += bv.x; acc.y += bv.y; acc.z += bv.z; acc.w += bv.w;
    acc_bf16row(acc, xwb, w, lane, dn * dn);
    store_bf16row(outb, w, lane, acc);
}

__global__ __launch_bounds__(256) void sage_gather_kernel(
    const __nv_bfloat16* __restrict__ hb, __nv_bfloat16* __restrict__ outb)
{
    int w = (blockIdx.x * blockDim.x + threadIdx.x) >> 5;
    int lane = threadIdx.x & 31;
    if (w >= N_NODES) return;
    int beg = g_rowstart[w], end = g_rowstart[w + 1];
    float4 acc = make_float4(0.f, 0.f, 0.f, 0.f);
    for (int b = beg; b < end; b += 32) {
        int nb = min(32, end - b);
        int s_l = 0;
        if (b + lane < end) s_l = g_csr[b + lane];
        for (int j = 0; j < nb; j++) {
            int s = __shfl_sync(0xffffffffu, s_l, j);
            acc_bf16row(acc, hb, s, lane, 1.0f);
        }
    }
    float rc = g_rcnt[w];
    acc.x *= rc; acc.y *= rc; acc.z *= rc; acc.w *= rc;
    store_bf16row(outb, w, lane, acc);
}

// ---------------- pooling (bf16 input) ----------------
__device__ __forceinline__ int lower_bound_batch(int val) {
    int lo = 0, hi = N_NODES;
    while (lo < hi) {
        int mid = (lo + hi) >> 1;
        if (g_batch[mid] < val) lo = mid + 1; else hi = mid;
    }
    return lo;
}

__global__ void pool_kernel(const __nv_bfloat16* __restrict__ h) {
    int g = blockIdx.x;
    int part = blockIdx.y;
    int f = threadIdx.x;
    int lo = lower_bound_batch(g);
    int hi = lower_bound_batch(g + 1);
    float acc = 0.f;
    for (int n = lo + part; n < hi; n += 8)
        acc += __bfloat162float(h[(size_t)n * 128 + f]);
    atomicAdd(&g_pool[g * 128 + f], acc);
    if (part == 0 && f == 0) g_gcnt[g] = max(hi - lo, 1);
}

// ---------------- classifier MLP + softmax ----------------
__global__ void mlp_kernel(
    const float* __restrict__ w0, const float* __restrict__ b0,
    const float* __restrict__ w1, const float* __restrict__ b1,
    const float* __restrict__ w2, const float* __restrict__ b2,
    const float* __restrict__ w3, const float* __restrict__ b3,
    const float* __restrict__ bn0g, const float* __restrict__ bn0b,
    const float* __restrict__ bn1g, const float* __restrict__ bn1b,
    const float* __restrict__ bn2g, const float* __restrict__ bn2b,
    float* __restrict__ out)
{
    __shared__ float sin_[128], h0[200], h1[100], h2[50], lg[10];
    int g = blockIdx.x, t = threadIdx.x;
    if (t < 128) sin_[t] = g_pool[g * 128 + t] / (float)g_gcnt[g];
    __syncthreads();
    const float bnc = rsqrtf(1.0f + 1e-5f);
    if (t < 200) {
        float s = b0[t];
        const float* wr = w0 + (size_t)t * 128;
#pragma unroll 4
        for (int k = 0; k < 128; k++) s += wr[k] * sin_[k];
        h0[t] = tanhf(s * bn0g[t] * bnc + bn0b[t]);
    }
    __syncthreads();
    if (t < 100) {
        float s = b1[t];
        const float* wr = w1 + (size_t)t * 200;
#pragma unroll 4
        for (int k = 0; k < 200; k++) s += wr[k] * h0[k];
        h1[t] = tanhf(s * bn1g[t] * bnc + bn1b[t]);
    }
    __syncthreads();
    if (t < 50) {
        float s = b2[t];
        const float* wr = w2 + (size_t)t * 100;
#pragma unroll 4
        for (int k = 0; k < 100; k++) s += wr[k] * h1[k];
        h2[t] = tanhf(s * bn2g[t] * bnc + bn2b[t]);
    }
    __syncthreads();
    if (t < 10) {
        float s = b3[t];
        const float* wr = w3 + (size_t)t * 50;
#pragma unroll
        for (int k = 0; k < 50; k++) s += wr[k] * h2[k];
        lg[t] = s;
    }
    __syncthreads();
    if (t == 0) {
        float m = lg[0];
        for (int c = 1; c < N_CLASSES; c++) m = fmaxf(m, lg[c]);
        float e[N_CLASSES];
        float sum = 0.f;
        for (int c = 0; c < N_CLASSES; c++) { e[c] = expf(lg[c] - m); sum += e[c]; }
        float inv = 1.0f / sum;
        for (int c = 0; c < N_CLASSES; c++) out[g * N_CLASSES + c] = e[c] * inv;
    }
}

// ---------------- launch ----------------
extern "C" void kernel_launch(void* const* d_in, const int* in_sizes, int n_in,
                              void* d_out, int out_size)
{
    const float* x       = (const float*)d_in[0];
    const void*  ei      = d_in[1];
    const void*  bt      = d_in[2];
    const float* gcn_w   = (const float*)d_in[3];
    const float* gcn_b   = (const float*)d_in[4];
    const float* s1_wl   = (const float*)d_in[5];
    const float* s1_bl   = (const float*)d_in[6];
    const float* s1_wr   = (const float*)d_in[7];
    const float* s2_wl   = (const float*)d_in[8];
    const float* s2_bl   = (const float*)d_in[9];
    const float* s2_wr   = (const float*)d_in[10];
    const float* c_w0 = (const float*)d_in[11]; const float* c_b0 = (const float*)d_in[12];
    const float* c_w1 = (const float*)d_in[13]; const float* c_b1 = (const float*)d_in[14];
    const float* c_w2 = (const float*)d_in[15]; const float* c_b2 = (const float*)d_in[16];
    const float* c_w3 = (const float*)d_in[17]; const float* c_b3 = (const float*)d_in[18];
    const float* bn0g = (const float*)d_in[19]; const float* bn0b = (const float*)d_in[20];
    const float* bn1g = (const float*)d_in[21]; const float* bn1b = (const float*)d_in[22];
    const float* bn2g = (const float*)d_in[23]; const float* bn2b = (const float*)d_in[24];
    float* out = (float*)d_out;

    __nv_bfloat16 *B1, *B2, *B3, *Bagg;
    uint32_t *Wg_hi, *Wg_lo, *W1l_hi, *W1l_lo, *W1r_hi, *W1r_lo;
    uint32_t *W2l_hi, *W2l_lo, *W2r_hi, *W2r_lo;
    cudaGetSymbolAddress((void**)&B1, g_B1);
    cudaGetSymbolAddress((void**)&B2, g_B2);
    cudaGetSymbolAddress((void**)&B3, g_B3);
    cudaGetSymbolAddress((void**)&Bagg, g_Bagg);
    cudaGetSymbolAddress((void**)&Wg_hi, g_Wg_hi);   cudaGetSymbolAddress((void**)&Wg_lo, g_Wg_lo);
    cudaGetSymbolAddress((void**)&W1l_hi, g_W1l_hi); cudaGetSymbolAddress((void**)&W1l_lo, g_W1l_lo);
    cudaGetSymbolAddress((void**)&W1r_hi, g_W1r_hi); cudaGetSymbolAddress((void**)&W1r_lo, g_W1r_lo);
    cudaGetSymbolAddress((void**)&W2l_hi, g_W2l_hi); cudaGetSymbolAddress((void**)&W2l_lo, g_W2l_lo);
    cudaGetSymbolAddress((void**)&W2r_hi, g_W2r_hi); cudaGetSymbolAddress((void**)&W2r_lo, g_W2r_lo);

    static cudaStream_t s_side = nullptr;
    static cudaEvent_t  s_fork = nullptr, s_join = nullptr;
    if (s_side == nullptr) {
        cudaStreamCreateWithFlags(&s_side, cudaStreamNonBlocking);
        cudaEventCreateWithFlags(&s_fork, cudaEventDisableTiming);
        cudaEventCreateWithFlags(&s_join, cudaEventDisableTiming);
        cudaFuncSetAttribute(gemm_dual,
                             cudaFuncAttributeMaxDynamicSharedMemorySize, GEMM_SMEM);
        cudaFuncSetAttribute(gemm_gcn,
                             cudaFuncAttributeMaxDynamicSharedMemorySize, GEMM_SMEM);
    }

    const int TB = 256;
    const int nodeBlocks   = (N_NODES + TB - 1) / TB;
    const int edgeBlocks   = (N_EDGES + TB - 1) / TB;
    const int gatherBlocks = (N_NODES + 7) / 8;
    const int gemmBlocks   = (N_NODES + 127) / 128;

    // fork at t=0: side stream does prepack + GCN GEMM, hidden under CSR build
    cudaEventRecord(s_fork, 0);
    cudaStreamWaitEvent(s_side, s_fork, 0);
    prepack_all<<<160, 256, 0, s_side>>>(gcn_w, s1_wl, s1_wr, s2_wl, s2_wr);
    gemm_gcn<<<gemmBlocks, 256, GEMM_SMEM, s_side>>>(x, Wg_hi, Wg_lo, B1, N_NODES);

    // main stream: index prep + CSR build
    detect_kernel<<<1, 256>>>(ei);
    zero_kernel<<<nodeBlocks, TB>>>();
    convert_hist_kernel<<<edgeBlocks, TB>>>(ei, bt);
    scan1_kernel<<<SCAN_NBLK, SCAN_BLK>>>();
    scan2_kernel<<<1, 128>>>();
    scan3_kernel<<<SCAN_NBLK, SCAN_BLK>>>();
    scatter_kernel<<<edgeBlocks, TB>>>();

    cudaEventRecord(s_join, s_side);
    cudaStreamWaitEvent(0, s_join, 0);

    // GCN aggregate: B2 = norm-agg(B1) + self(B1)*dinv^2 + bias
    gcn_gather_kernel<<<gatherBlocks, 256>>>(B1, B2, gcn_b);

    // SAGE1: Bagg = mean-agg(B2); B3 = Bagg@W1l + bl + B2@W1r
    sage_gather_kernel<<<gatherBlocks, 256>>>(B2, Bagg);
    gemm_dual<<<gemmBlocks, 256, GEMM_SMEM>>>(Bagg, W1l_hi, W1l_lo, B2, W1r_hi, W1r_lo,
                                              s1_bl, B3, N_NODES);

    // SAGE2: Bagg = mean-agg(B3); B1 = Bagg@W2l + bl + B3@W2r
    sage_gather_kernel<<<gatherBlocks, 256>>>(B3, Bagg);
    gemm_dual<<<gemmBlocks, 256, GEMM_SMEM>>>(Bagg, W2l_hi, W2l_lo, B3, W2r_hi, W2r_lo,
                                              s2_bl, B1, N_NODES);

    // pool + classifier
    dim3 pg(N_GRAPHS, 8);
    pool_kernel<<<pg, 128>>>(B1);
    mlp_kernel<<<N_GRAPHS, 256>>>(c_w0, c_b0, c_w1, c_b1, c_w2, c_b2, c_w3, c_b3,
                                  bn0g, bn0b, bn1g, bn1b, bn2g, bn2b, out);
}